// round 15
// baseline (speedup 1.0000x reference)
#include <cuda_runtime.h>
#include <cuda_bf16.h>
#include <cstdint>

// ---------------------------------------------------------------------------
// ConvMultiheadAttention: B=8, S=1024, D=512, H=8, hd=64, KERNEL=3
// out  = [8,1024,512]  ; ave = [8,1024,1024]
// ---------------------------------------------------------------------------

#define BB 8
#define SS 1024
#define DD 512
#define HH 8
#define HD 64

typedef unsigned long long ull;

// ----- bf16 split helpers ----------------------------------------------------
__device__ __forceinline__ void bsplit2(float u, float v, uint32_t& ph, uint32_t& pl) {
    __nv_bfloat16 hu = __float2bfloat16_rn(u);
    __nv_bfloat16 hv = __float2bfloat16_rn(v);
    __nv_bfloat16 lu = __float2bfloat16_rn(u - __bfloat162float(hu));
    __nv_bfloat16 lv = __float2bfloat16_rn(v - __bfloat162float(hv));
    ph = (uint32_t)__bfloat16_as_ushort(hu) | ((uint32_t)__bfloat16_as_ushort(hv) << 16);
    pl = (uint32_t)__bfloat16_as_ushort(lu) | ((uint32_t)__bfloat16_as_ushort(lv) << 16);
}
__device__ __forceinline__ void mma_bf16s(float4& d, uint32_t a0, uint32_t a1,
                                          uint32_t a2, uint32_t a3,
                                          uint32_t b0, uint32_t b1) {
    asm("mma.sync.aligned.m16n8k16.row.col.f32.bf16.bf16.f32 "
        "{%0,%1,%2,%3}, {%4,%5,%6,%7}, {%8,%9}, {%0,%1,%2,%3};"
        : "+f"(d.x), "+f"(d.y), "+f"(d.z), "+f"(d.w)
        : "r"(a0), "r"(a1), "r"(a2), "r"(a3), "r"(b0), "r"(b1));
}
__device__ __forceinline__ void ldsm4(uint32_t& r0, uint32_t& r1, uint32_t& r2,
                                      uint32_t& r3, uint32_t addr) {
    asm volatile("ldmatrix.sync.aligned.m8n8.x4.shared.b16 {%0,%1,%2,%3}, [%4];"
        : "=r"(r0), "=r"(r1), "=r"(r2), "=r"(r3) : "r"(addr));
}

// ----- scratch (static device globals) --------------------------------------
// All packed arrays use PLAIN kpair order (ldmatrix supplies the fragment
// permutation in hardware).
__device__ uint32_t g_xh[3][BB][SS][256];    // inputs split hi
__device__ uint32_t g_xl[3][BB][SS][256];    // inputs split lo
__device__ uint32_t g_wh[4][3][DD][256];     // weights split hi, per tap (3=Wo)
__device__ uint32_t g_wl[4][3][DD][256];     // weights split lo
__device__ uint32_t g_sqh[BB * HH][SS][32];  // Q/64 split hi
__device__ uint32_t g_sql[BB * HH][SS][32];
__device__ uint32_t g_skh[BB * HH][SS][32];  // K split hi
__device__ uint32_t g_skl[BB * HH][SS][32];
__device__ float g_p[(size_t)BB * HH * SS * SS]; // raw scores
__device__ uint32_t g_ph[BB * HH][SS][512];  // probs split hi
__device__ uint32_t g_pl[BB * HH][SS][512];  // probs split lo
__device__ uint32_t g_vh[BB * HH][HD][512];  // V split hi
__device__ uint32_t g_vl[BB * HH][HD][512];  // V split lo
__device__ uint32_t g_oh[BB * SS][256];      // o1 split hi
__device__ uint32_t g_ol[BB * SS][256];      // o1 split lo

// ---------------------------------------------------------------------------
// Kernel 1: xprep — split inputs [B,S,D] into kpair-packed bf16 hi/lo (plain)
// ---------------------------------------------------------------------------
__global__ void xprep_kernel(const float* __restrict__ q,
                             const float* __restrict__ k,
                             const float* __restrict__ v) {
    const int tn = blockIdx.z, b = blockIdx.y, s0 = blockIdx.x * 128;
    const float* src = (tn == 0) ? q : (tn == 1) ? k : v;
    const int kp = threadIdx.x;             // 0..255
    for (int i = 0; i < 128; i++) {
        int s = s0 + i;
        float2 uv = *(const float2*)&src[((size_t)b * SS + s) * DD + 2 * kp];
        uint32_t ph, pl;
        bsplit2(uv.x, uv.y, ph, pl);
        g_xh[tn][b][s][kp] = ph;
        g_xl[tn][b][s][kp] = pl;
    }
}

// ---------------------------------------------------------------------------
// Kernel 2: wprep — split weights (Wq/Wk/Wv per tap, Wo) into plain hi/lo.
// ---------------------------------------------------------------------------
__global__ void wprep_kernel(const float* __restrict__ Wq,
                             const float* __restrict__ Wk,
                             const float* __restrict__ Wv,
                             const float* __restrict__ Wo) {
    const int tn = blockIdx.y;
    const float* W = (tn == 0) ? Wq : (tn == 1) ? Wk : (tn == 2) ? Wv : Wo;
    const int KER = (tn == 0 || tn == 1) ? 3 : 1;
    const int Kdim = DD * KER;
    const int co0 = blockIdx.x * 64;
    const int kp = threadIdx.x;              // 0..255 (ci pair)
    for (int tap = 0; tap < KER; tap++)
        for (int i = 0; i < 64; i++) {
            int co = co0 + i;
            float u = W[(size_t)co * Kdim + (2 * kp) * KER + tap];
            float vv = W[(size_t)co * Kdim + (2 * kp + 1) * KER + tap];
            uint32_t ph, pl;
            bsplit2(u, vv, ph, pl);
            g_wh[tn][tap][co][kp] = ph;
            g_wl[tn][tap][co][kp] = pl;
        }
}

// ---------------------------------------------------------------------------
// Kernel 3: conv1d as tap-decomposed bf16 MMA GEMM (split, 3 terms), LDSM
// fragment loads. ALL epilogues emit packed bf16 hi/lo directly:
//   Q/K: d-kpairs via shfl_xor(4) row-pair exchange -> g_sqh/g_sql/g_skh/g_skl
//   V:   s-kpairs (adjacent cols in-thread)        -> g_vh/g_vl
// No fp32 intermediate; qkprep deleted.
// ---------------------------------------------------------------------------
#define CV_ST 20
#define CV_AH 0
#define CV_AL 2560
#define CV_BH 5120
#define CV_BL 7680
#define CV_BUF_U32 10240
#define CV_SMEM (2 * CV_BUF_U32 * (int)sizeof(uint32_t))

__global__ __launch_bounds__(256, 2)
void conv_mma(const float* __restrict__ bq, const float* __restrict__ bk,
              const float* __restrict__ bv) {
    extern __shared__ uint32_t smu[];
    __shared__ float s_bias[128];

    const int zz = blockIdx.z, tn = zz / BB, b = zz % BB;
    const float* bias = (tn == 0) ? bq : (tn == 1) ? bk : bv;
    const int KER = (tn == 2) ? 1 : 3;
    const int pad = KER >> 1;
    const int NIT = KER * 16;
    const int m0 = blockIdx.x * 128, n0 = blockIdx.y * 128;
    const int tid = threadIdx.x, wid = tid >> 5, lane = tid & 31;
    const int g = lane >> 2, tg = lane & 3;
    const int wm = (wid >> 2) * 64, wn = (wid & 3) * 32;
    const int lt = lane >> 3, ro = lane & 7;   // ldsm tile index, row offset

    if (tid < 128) s_bias[tid] = bias[m0 + tid];

    const uint32_t sbase = (uint32_t)__cvta_generic_to_shared(smu);

    float4 dacc[4][4];
    #pragma unroll
    for (int mi = 0; mi < 4; mi++)
        #pragma unroll
        for (int ni = 0; ni < 4; ni++) dacc[mi][ni] = make_float4(0.f, 0.f, 0.f, 0.f);

    const int a_row = tid >> 1, a_half = (tid & 1) * 8;
    const int b_s = tid & 127, b_half = (tid >> 7) * 8;

    uint4 rah0, rah1, ral0, ral1, rbh0, rbh1, rbl0, rbl1;

    auto ldg_slab = [&](int it) {
        int tap = it >> 4, c = it & 15;
        const uint32_t* wh = &g_wh[tn][tap][m0 + a_row][c * 16 + a_half];
        const uint32_t* wl = &g_wl[tn][tap][m0 + a_row][c * 16 + a_half];
        rah0 = *(const uint4*)&wh[0]; rah1 = *(const uint4*)&wh[4];
        ral0 = *(const uint4*)&wl[0]; ral1 = *(const uint4*)&wl[4];
        int s_glob = n0 + b_s + tap - pad;
        if ((unsigned)s_glob < (unsigned)SS) {
            const uint32_t* xh = &g_xh[tn][b][s_glob][c * 16 + b_half];
            const uint32_t* xl = &g_xl[tn][b][s_glob][c * 16 + b_half];
            rbh0 = *(const uint4*)&xh[0]; rbh1 = *(const uint4*)&xh[4];
            rbl0 = *(const uint4*)&xl[0]; rbl1 = *(const uint4*)&xl[4];
        } else {
            rbh0 = make_uint4(0, 0, 0, 0); rbh1 = rbh0;
            rbl0 = rbh0; rbl1 = rbh0;
        }
    };
    auto sts_slab = [&](int bf) {
        uint32_t* Ah = smu + bf * CV_BUF_U32 + CV_AH + a_row * CV_ST + a_half;
        uint32_t* Al = smu + bf * CV_BUF_U32 + CV_AL + a_row * CV_ST + a_half;
        uint32_t* Bh = smu + bf * CV_BUF_U32 + CV_BH + b_s * CV_ST + b_half;
        uint32_t* Bl = smu + bf * CV_BUF_U32 + CV_BL + b_s * CV_ST + b_half;
        *(uint4*)&Ah[0] = rah0; *(uint4*)&Ah[4] = rah1;
        *(uint4*)&Al[0] = ral0; *(uint4*)&Al[4] = ral1;
        *(uint4*)&Bh[0] = rbh0; *(uint4*)&Bh[4] = rbh1;
        *(uint4*)&Bl[0] = rbl0; *(uint4*)&Bl[4] = rbl1;
    };

    ldg_slab(0);
    sts_slab(0);
    __syncthreads();

    for (int it = 0; it < NIT; it++) {
        const int bf = it & 1;
        const bool have = (it + 1) < NIT;
        if (have) ldg_slab(it + 1);

        const uint32_t bufB = sbase + 4 * (bf * CV_BUF_U32);
        #pragma unroll
        for (int s = 0; s < 2; s++) {
            uint32_t bh[4][2], bl[4][2];
            #pragma unroll
            for (int p = 0; p < 2; p++) {
                uint32_t off = (wn + (2 * p + (lt >> 1)) * 8 + ro) * CV_ST
                             + s * 8 + (lt & 1) * 4;
                uint32_t r0, r1, r2, r3;
                ldsm4(r0, r1, r2, r3, bufB + 4 * (CV_BH + off));
                bh[2 * p][0] = r0; bh[2 * p][1] = r1;
                bh[2 * p + 1][0] = r2; bh[2 * p + 1][1] = r3;
                ldsm4(r0, r1, r2, r3, bufB + 4 * (CV_BL + off));
                bl[2 * p][0] = r0; bl[2 * p][1] = r1;
                bl[2 * p + 1][0] = r2; bl[2 * p + 1][1] = r3;
            }
            #pragma unroll
            for (int mi = 0; mi < 4; mi++) {
                uint32_t aoff = (wm + mi * 16 + (lt & 1) * 8 + ro) * CV_ST
                              + s * 8 + (lt >> 1) * 4;
                uint32_t a0, a1, a2, a3, l0, l1, l2, l3;
                ldsm4(a0, a1, a2, a3, bufB + 4 * (CV_AH + aoff));
                ldsm4(l0, l1, l2, l3, bufB + 4 * (CV_AL + aoff));
                #pragma unroll
                for (int ni = 0; ni < 4; ni++) {
                    mma_bf16s(dacc[mi][ni], a0, a1, a2, a3, bh[ni][0], bh[ni][1]);
                    mma_bf16s(dacc[mi][ni], a0, a1, a2, a3, bl[ni][0], bl[ni][1]);
                    mma_bf16s(dacc[mi][ni], l0, l1, l2, l3, bh[ni][0], bh[ni][1]);
                }
            }
        }

        if (have) sts_slab(bf ^ 1);
        __syncthreads();
    }

    if (tn != 2) {
        // Q/K: pack d-kpairs via row-pair exchange (lane ^ 4 swaps g parity)
        const float scale = (tn == 0) ? 0.015625f : 1.0f;
        uint32_t (*dsth)[SS][32] = (tn == 0) ? g_sqh : g_skh;
        uint32_t (*dstl)[SS][32] = (tn == 0) ? g_sql : g_skl;
        #pragma unroll
        for (int mi = 0; mi < 4; mi++) {
            int r = wm + mi * 16 + g;
            float b0 = s_bias[r], b1 = s_bias[r + 8];
            #pragma unroll
            for (int ni = 0; ni < 4; ni++) {
                float4 d = dacc[mi][ni];
                float v0 = (d.x + b0) * scale, v1 = (d.y + b0) * scale;
                float v2 = (d.z + b1) * scale, v3 = (d.w + b1) * scale;
                float p0 = __shfl_xor_sync(0xffffffffu, v0, 4);
                float p1 = __shfl_xor_sync(0xffffffffu, v1, 4);
                float p2 = __shfl_xor_sync(0xffffffffu, v2, 4);
                float p3 = __shfl_xor_sync(0xffffffffu, v3, 4);
                if ((g & 1) == 0) {
                    int col = n0 + wn + ni * 8 + 2 * tg;
                    int d0g = m0 + r;                 // even row
                    int d1g = d0g + 8;
                    int bh0 = b * HH + (d0g >> 6), kp0 = (d0g & 63) >> 1;
                    int bh1 = b * HH + (d1g >> 6), kp1 = (d1g & 63) >> 1;
                    uint32_t ph, pl;
                    bsplit2(v0, p0, ph, pl);
                    dsth[bh0][col][kp0] = ph; dstl[bh0][col][kp0] = pl;
                    bsplit2(v1, p1, ph, pl);
                    dsth[bh0][col + 1][kp0] = ph; dstl[bh0][col + 1][kp0] = pl;
                    bsplit2(v2, p2, ph, pl);
                    dsth[bh1][col][kp1] = ph; dstl[bh1][col][kp1] = pl;
                    bsplit2(v3, p3, ph, pl);
                    dsth[bh1][col + 1][kp1] = ph; dstl[bh1][col + 1][kp1] = pl;
                }
            }
        }
    } else {
        // V: emit packed bf16 hi/lo directly (kpair over s = adjacent cols)
        #pragma unroll
        for (int mi = 0; mi < 4; mi++) {
            int lr0 = wm + mi * 16 + g;
            float b0 = s_bias[lr0], b1 = s_bias[lr0 + 8];
            int row0 = m0 + lr0, row1 = row0 + 8;
            int bh0 = b * HH + (row0 >> 6), bh1 = b * HH + (row1 >> 6);
            int dd0 = row0 & 63, dd1 = row1 & 63;
            #pragma unroll
            for (int ni = 0; ni < 4; ni++) {
                int kp = (n0 + wn + ni * 8 + 2 * tg) >> 1;
                float4 d = dacc[mi][ni];
                uint32_t ph, pl;
                bsplit2(d.x + b0, d.y + b0, ph, pl);
                g_vh[bh0][dd0][kp] = ph; g_vl[bh0][dd0][kp] = pl;
                bsplit2(d.z + b1, d.w + b1, ph, pl);
                g_vh[bh1][dd1][kp] = ph; g_vl[bh1][dd1][kp] = pl;
            }
        }
    }
}

// ---------------------------------------------------------------------------
// Kernel 4: scores GEMM via bf16 mma (3 terms), LDSM fragment loads.
// smem stride 36 u32. Raw scores -> g_p.
// ---------------------------------------------------------------------------
#define SG_ST 36
#define SG_A_H 0
#define SG_A_L 4608
#define SG_B_H 9216
#define SG_B_L 13824
#define SG_SMEM (18432 * (int)sizeof(uint32_t))

__global__ __launch_bounds__(256, 2) void scores_gemm() {
    extern __shared__ uint32_t smu[];
    const int b = blockIdx.z, h = blockIdx.y;
    const int s0 = (blockIdx.x >> 3) * 128, t0 = (blockIdx.x & 7) * 128;
    const int bh = b * HH + h;
    const int tid = threadIdx.x, wid = tid >> 5, lane = tid & 31;
    const int g = lane >> 2, tg = lane & 3;
    const int wm = (wid >> 2) * 64, wn = (wid & 3) * 32;
    const int lt = lane >> 3, ro = lane & 7;

    const uint32_t sbase = (uint32_t)__cvta_generic_to_shared(smu);

    {
        const int row = tid >> 1, c0 = (tid & 1) * 16;
        const uint32_t* sa_h = &g_sqh[bh][s0 + row][c0];
        const uint32_t* sa_l = &g_sql[bh][s0 + row][c0];
        const uint32_t* sb_h = &g_skh[bh][t0 + row][c0];
        const uint32_t* sb_l = &g_skl[bh][t0 + row][c0];
        uint32_t* Ah = smu + SG_A_H + row * SG_ST + c0;
        uint32_t* Al = smu + SG_A_L + row * SG_ST + c0;
        uint32_t* Bh = smu + SG_B_H + row * SG_ST + c0;
        uint32_t* Bl = smu + SG_B_L + row * SG_ST + c0;
        #pragma unroll
        for (int i = 0; i < 4; i++) {
            *(uint4*)&Ah[4 * i] = *(const uint4*)&sa_h[4 * i];
            *(uint4*)&Al[4 * i] = *(const uint4*)&sa_l[4 * i];
            *(uint4*)&Bh[4 * i] = *(const uint4*)&sb_h[4 * i];
            *(uint4*)&Bl[4 * i] = *(const uint4*)&sb_l[4 * i];
        }
    }
    __syncthreads();

    float4 dacc[4][4];
    #pragma unroll
    for (int mi = 0; mi < 4; mi++)
        #pragma unroll
        for (int ni = 0; ni < 4; ni++) dacc[mi][ni] = make_float4(0.f, 0.f, 0.f, 0.f);

    #pragma unroll
    for (int s = 0; s < 4; s++) {
        uint32_t bh2[4][2], bl2[4][2];
        #pragma unroll
        for (int p = 0; p < 2; p++) {
            uint32_t off = (wn + (2 * p + (lt >> 1)) * 8 + ro) * SG_ST
                         + s * 8 + (lt & 1) * 4;
            uint32_t r0, r1, r2, r3;
            ldsm4(r0, r1, r2, r3, sbase + 4 * (SG_B_H + off));
            bh2[2 * p][0] = r0; bh2[2 * p][1] = r1;
            bh2[2 * p + 1][0] = r2; bh2[2 * p + 1][1] = r3;
            ldsm4(r0, r1, r2, r3, sbase + 4 * (SG_B_L + off));
            bl2[2 * p][0] = r0; bl2[2 * p][1] = r1;
            bl2[2 * p + 1][0] = r2; bl2[2 * p + 1][1] = r3;
        }
        #pragma unroll
        for (int mi = 0; mi < 4; mi++) {
            uint32_t aoff = (wm + mi * 16 + (lt & 1) * 8 + ro) * SG_ST
                          + s * 8 + (lt >> 1) * 4;
            uint32_t a0, a1, a2, a3, l0, l1, l2, l3;
            ldsm4(a0, a1, a2, a3, sbase + 4 * (SG_A_H + aoff));
            ldsm4(l0, l1, l2, l3, sbase + 4 * (SG_A_L + aoff));
            #pragma unroll
            for (int ni = 0; ni < 4; ni++) {
                mma_bf16s(dacc[mi][ni], a0, a1, a2, a3, bh2[ni][0], bh2[ni][1]);
                mma_bf16s(dacc[mi][ni], a0, a1, a2, a3, bl2[ni][0], bl2[ni][1]);
                mma_bf16s(dacc[mi][ni], l0, l1, l2, l3, bh2[ni][0], bh2[ni][1]);
            }
        }
    }

    float* Pg = &g_p[((size_t)bh << 20)];
    #pragma unroll
    for (int mi = 0; mi < 4; mi++) {
        int lr0 = s0 + wm + mi * 16 + g;
        #pragma unroll
        for (int ni = 0; ni < 4; ni++) {
            int col = t0 + wn + ni * 8 + 2 * tg;
            float4 d = dacc[mi][ni];
            *(float2*)&Pg[(size_t)lr0 * SS + col]       = make_float2(d.x, d.y);
            *(float2*)&Pg[(size_t)(lr0 + 8) * SS + col] = make_float2(d.z, d.w);
        }
    }
}

// ---------------------------------------------------------------------------
// Kernel 5: softmax + fused ave + plain packed bf16 split P emission.
// ---------------------------------------------------------------------------
#define SMA_SMEM (16384 * (int)sizeof(float))

__global__ __launch_bounds__(256) void softmax_ave(float* __restrict__ ave) {
    extern __shared__ float smf[];
    float* buf = smf;            // 8*1024
    float* av  = smf + 8192;     // 8*1024

    const int b = blockIdx.y, s0 = blockIdx.x * 8;
    const int tid = threadIdx.x, w = tid >> 5, lane = tid & 31;

    #pragma unroll
    for (int i = 0; i < 8; i++)
        *(float4*)&av[(i * 256 + tid) * 4] = make_float4(0.f, 0.f, 0.f, 0.f);

    for (int h = 0; h < HH; h++) {
        const int bh = b * HH + h;
        const float* Pg = &g_p[(((size_t)bh) << 20) + (size_t)s0 * SS];
        __syncthreads();
        #pragma unroll
        for (int i = 0; i < 8; i++) {
            int off = (i * 256 + tid) * 4;
            *(float4*)&buf[off] = *(const float4*)&Pg[off];
        }
        __syncthreads();

        {
            float* row = &buf[w * 1024];
            float* arow = &av[w * 1024];
            float m = -1e30f;
            for (int j = lane; j < 1024; j += 32) m = fmaxf(m, row[j]);
            #pragma unroll
            for (int o = 16; o > 0; o >>= 1)
                m = fmaxf(m, __shfl_xor_sync(0xffffffffu, m, o));
            float s = 0.0f;
            for (int j = lane; j < 1024; j += 32) {
                float e = __expf(row[j] - m);
                row[j] = e;
                s += e;
            }
            #pragma unroll
            for (int o = 16; o > 0; o >>= 1) s += __shfl_xor_sync(0xffffffffu, s, o);
            float inv = 1.0f / s;
            for (int j = lane; j < 1024; j += 32) {
                float p = row[j] * inv;
                row[j] = p;
                arow[j] += 0.125f * p;
            }
        }
        __syncthreads();

        #pragma unroll
        for (int i = 0; i < 16; i++) {
            int tt = i * 256 + tid;          // 0..4095
            int r = tt >> 9, kk = tt & 511;
            float2 uv = *(float2*)&buf[r * 1024 + 2 * kk];
            uint32_t ph, pl;
            bsplit2(uv.x, uv.y, ph, pl);
            g_ph[bh][s0 + r][kk] = ph;
            g_pl[bh][s0 + r][kk] = pl;
        }
    }

    __syncthreads();
    #pragma unroll
    for (int i = 0; i < 8; i++) {
        int off = (i * 256 + tid) * 4;
        int r = off >> 10, c = off & 1023;
        *(float4*)&ave[((size_t)b * SS + s0 + r) * SS + c] = *(float4*)&av[off];
    }
}

// ---------------------------------------------------------------------------
// Kernel 6: PV GEMM via bf16 mma (3 terms), LDSM fragment loads.
// smem stride 20 u32. Epilogue emits plain packed o1.
// ---------------------------------------------------------------------------
#define PV_ST 20
#define PV_A_H 0
#define PV_A_L 2560
#define PV_B_H 5120
#define PV_B_L 6400
#define PV_BUF_U32 7680
#define PV_SMEM (2 * PV_BUF_U32 * (int)sizeof(uint32_t))

__global__ __launch_bounds__(256, 2) void pv_mma() {
    extern __shared__ uint32_t smu[];
    const int b = blockIdx.z, h = blockIdx.y, s0 = blockIdx.x * 128;
    const int bh = b * HH + h;
    const int tid = threadIdx.x, wid = tid >> 5, lane = tid & 31;
    const int g = lane >> 2, tg = lane & 3;
    const int wm = (wid >> 2) * 64, wn = (wid & 3) * 16;
    const int lt = lane >> 3, ro = lane & 7;

    const uint32_t sbase = (uint32_t)__cvta_generic_to_shared(smu);

    float4 dacc[4][2];
    #pragma unroll
    for (int mi = 0; mi < 4; mi++)
        #pragma unroll
        for (int ni = 0; ni < 2; ni++) dacc[mi][ni] = make_float4(0.f, 0.f, 0.f, 0.f);

    const int a_row = tid >> 1, a_c0 = (tid & 1) * 8;
    const int b_d = tid >> 2, b_c0 = (tid & 3) * 4;

    uint4 rah0, rah1, ral0, ral1, rbh, rbl;

    auto ldg_slab = [&](int c) {
        const uint32_t* ph = &g_ph[bh][s0 + a_row][c * 16 + a_c0];
        const uint32_t* pl = &g_pl[bh][s0 + a_row][c * 16 + a_c0];
        rah0 = *(const uint4*)&ph[0]; rah1 = *(const uint4*)&ph[4];
        ral0 = *(const uint4*)&pl[0]; ral1 = *(const uint4*)&pl[4];
        rbh = *(const uint4*)&g_vh[bh][b_d][c * 16 + b_c0];
        rbl = *(const uint4*)&g_vl[bh][b_d][c * 16 + b_c0];
    };
    auto sts_slab = [&](int bf) {
        uint32_t* Ah = smu + bf * PV_BUF_U32 + PV_A_H + a_row * PV_ST + a_c0;
        uint32_t* Al = smu + bf * PV_BUF_U32 + PV_A_L + a_row * PV_ST + a_c0;
        uint32_t* Bh = smu + bf * PV_BUF_U32 + PV_B_H + b_d * PV_ST + b_c0;
        uint32_t* Bl = smu + bf * PV_BUF_U32 + PV_B_L + b_d * PV_ST + b_c0;
        *(uint4*)&Ah[0] = rah0; *(uint4*)&Ah[4] = rah1;
        *(uint4*)&Al[0] = ral0; *(uint4*)&Al[4] = ral1;
        *(uint4*)&Bh[0] = rbh;
        *(uint4*)&Bl[0] = rbl;
    };

    ldg_slab(0);
    sts_slab(0);
    __syncthreads();

    for (int c = 0; c < 32; c++) {
        const int bf = c & 1;
        const bool have = (c + 1) < 32;
        if (have) ldg_slab(c + 1);

        const uint32_t bufB = sbase + 4 * (bf * PV_BUF_U32);
        #pragma unroll
        for (int s = 0; s < 2; s++) {
            uint32_t bh2[2][2], bl2[2][2];
            {
                uint32_t off = (wn + (lt >> 1) * 8 + ro) * PV_ST
                             + s * 8 + (lt & 1) * 4;
                uint32_t r0, r1, r2, r3;
                ldsm4(r0, r1, r2, r3, bufB + 4 * (PV_B_H + off));
                bh2[0][0] = r0; bh2[0][1] = r1; bh2[1][0] = r2; bh2[1][1] = r3;
                ldsm4(r0, r1, r2, r3, bufB + 4 * (PV_B_L + off));
                bl2[0][0] = r0; bl2[0][1] = r1; bl2[1][0] = r2; bl2[1][1] = r3;
            }
            #pragma unroll
            for (int mi = 0; mi < 4; mi++) {
                uint32_t aoff = (wm + mi * 16 + (lt & 1) * 8 + ro) * PV_ST
                              + s * 8 + (lt >> 1) * 4;
                uint32_t a0, a1, a2, a3, l0, l1, l2, l3;
                ldsm4(a0, a1, a2, a3, bufB + 4 * (PV_A_H + aoff));
                ldsm4(l0, l1, l2, l3, bufB + 4 * (PV_A_L + aoff));
                #pragma unroll
                for (int ni = 0; ni < 2; ni++) {
                    mma_bf16s(dacc[mi][ni], a0, a1, a2, a3, bh2[ni][0], bh2[ni][1]);
                    mma_bf16s(dacc[mi][ni], a0, a1, a2, a3, bl2[ni][0], bl2[ni][1]);
                    mma_bf16s(dacc[mi][ni], l0, l1, l2, l3, bh2[ni][0], bh2[ni][1]);
                }
            }
        }

        if (have) sts_slab(bf ^ 1);
        __syncthreads();
    }

    // epilogue: pack (col, col+1) pairs = one kpair over d (plain order)
    #pragma unroll
    for (int mi = 0; mi < 4; mi++) {
        int lr0 = s0 + wm + mi * 16 + g;
        int row0 = b * SS + lr0, row1 = row0 + 8;
        #pragma unroll
        for (int ni = 0; ni < 2; ni++) {
            int kp = (h * HD + wn + ni * 8 + 2 * tg) >> 1;
            float4 d = dacc[mi][ni];
            uint32_t ph, pl;
            bsplit2(d.x, d.y, ph, pl);
            g_oh[row0][kp] = ph; g_ol[row0][kp] = pl;
            bsplit2(d.z, d.w, ph, pl);
            g_oh[row1][kp] = ph; g_ol[row1][kp] = pl;
        }
    }
}

// ---------------------------------------------------------------------------
// Kernel 7: output projection via bf16 mma (3 terms), LDSM fragment loads.
// ---------------------------------------------------------------------------
__global__ __launch_bounds__(256, 2) void proj_mma(const float* __restrict__ bo,
                                                   float* __restrict__ out) {
    extern __shared__ uint32_t smu[];
    const int m0 = blockIdx.x * 128, n0 = blockIdx.y * 128;
    const int tid = threadIdx.x, wid = tid >> 5, lane = tid & 31;
    const int g = lane >> 2, tg = lane & 3;
    const int wm = (wid >> 2) * 64, wn = (wid & 3) * 32;
    const int lt = lane >> 3, ro = lane & 7;

    const uint32_t sbase = (uint32_t)__cvta_generic_to_shared(smu);

    float4 dacc[4][4];
    #pragma unroll
    for (int mi = 0; mi < 4; mi++)
        #pragma unroll
        for (int ni = 0; ni < 4; ni++) dacc[mi][ni] = make_float4(0.f, 0.f, 0.f, 0.f);

    const int a_row = tid >> 1, a_half = (tid & 1) * 8;

    uint4 rah0, rah1, ral0, ral1, rbh0, rbh1, rbl0, rbl1;

    auto ldg_slab = [&](int c) {
        const uint32_t* oh = &g_oh[m0 + a_row][c * 16 + a_half];
        const uint32_t* ol = &g_ol[m0 + a_row][c * 16 + a_half];
        rah0 = *(const uint4*)&oh[0]; rah1 = *(const uint4*)&oh[4];
        ral0 = *(const uint4*)&ol[0]; ral1 = *(const uint4*)&ol[4];
        const uint32_t* wh = &g_wh[3][0][n0 + a_row][c * 16 + a_half];
        const uint32_t* wl = &g_wl[3][0][n0 + a_row][c * 16 + a_half];
        rbh0 = *(const uint4*)&wh[0]; rbh1 = *(const uint4*)&wh[4];
        rbl0 = *(const uint4*)&wl[0]; rbl1 = *(const uint4*)&wl[4];
    };
    auto sts_slab = [&](int bf) {
        uint32_t* Ah = smu + bf * CV_BUF_U32 + CV_AH + a_row * CV_ST + a_half;
        uint32_t* Al = smu + bf * CV_BUF_U32 + CV_AL + a_row * CV_ST + a_half;
        uint32_t* Bh = smu + bf * CV_BUF_U32 + CV_BH + a_row * CV_ST + a_half;
        uint32_t* Bl = smu + bf * CV_BUF_U32 + CV_BL + a_row * CV_ST + a_half;
        *(uint4*)&Ah[0] = rah0; *(uint4*)&Ah[4] = rah1;
        *(uint4*)&Al[0] = ral0; *(uint4*)&Al[4] = ral1;
        *(uint4*)&Bh[0] = rbh0; *(uint4*)&Bh[4] = rbh1;
        *(uint4*)&Bl[0] = rbl0; *(uint4*)&Bl[4] = rbl1;
    };

    ldg_slab(0);
    sts_slab(0);
    __syncthreads();

    for (int c = 0; c < 16; c++) {
        const int bf = c & 1;
        const bool have = (c + 1) < 16;
        if (have) ldg_slab(c + 1);

        const uint32_t bufB = sbase + 4 * (bf * CV_BUF_U32);
        #pragma unroll
        for (int s = 0; s < 2; s++) {
            uint32_t bh[4][2], bl[4][2];
            #pragma unroll
            for (int p = 0; p < 2; p++) {
                uint32_t off = (wn + (2 * p + (lt >> 1)) * 8 + ro) * CV_ST
                             + s * 8 + (lt & 1) * 4;
                uint32_t r0, r1, r2, r3;
                ldsm4(r0, r1, r2, r3, bufB + 4 * (CV_BH + off));
                bh[2 * p][0] = r0; bh[2 * p][1] = r1;
                bh[2 * p + 1][0] = r2; bh[2 * p + 1][1] = r3;
                ldsm4(r0, r1, r2, r3, bufB + 4 * (CV_BL + off));
                bl[2 * p][0] = r0; bl[2 * p][1] = r1;
                bl[2 * p + 1][0] = r2; bl[2 * p + 1][1] = r3;
            }
            #pragma unroll
            for (int mi = 0; mi < 4; mi++) {
                uint32_t aoff = (wm + mi * 16 + (lt & 1) * 8 + ro) * CV_ST
                              + s * 8 + (lt >> 1) * 4;
                uint32_t a0, a1, a2, a3, l0, l1, l2, l3;
                ldsm4(a0, a1, a2, a3, bufB + 4 * (CV_AH + aoff));
                ldsm4(l0, l1, l2, l3, bufB + 4 * (CV_AL + aoff));
                #pragma unroll
                for (int ni = 0; ni < 4; ni++) {
                    mma_bf16s(dacc[mi][ni], a0, a1, a2, a3, bh[ni][0], bh[ni][1]);
                    mma_bf16s(dacc[mi][ni], a0, a1, a2, a3, bl[ni][0], bl[ni][1]);
                    mma_bf16s(dacc[mi][ni], l0, l1, l2, l3, bh[ni][0], bh[ni][1]);
                }
            }
        }

        if (have) sts_slab(bf ^ 1);
        __syncthreads();
    }

    #pragma unroll
    for (int mi = 0; mi < 4; mi++) {
        int lr0 = m0 + wm + mi * 16 + g;
        #pragma unroll
        for (int ni = 0; ni < 4; ni++) {
            int col = n0 + wn + ni * 8 + 2 * tg;
            float2 bb = *(const float2*)&bo[col];
            float4 d = dacc[mi][ni];
            *(float2*)&out[(size_t)lr0 * DD + col]       = make_float2(d.x + bb.x, d.y + bb.y);
            *(float2*)&out[(size_t)(lr0 + 8) * DD + col] = make_float2(d.z + bb.x, d.w + bb.y);
        }
    }
}

// ---------------------------------------------------------------------------
extern "C" void kernel_launch(void* const* d_in, const int* in_sizes, int n_in,
                              void* d_out, int out_size) {
    const float* query = (const float*)d_in[0];
    const float* key_t = (const float*)d_in[1];
    const float* value = (const float*)d_in[2];
    const float* Wq    = (const float*)d_in[3];
    const float* bq    = (const float*)d_in[4];
    const float* Wk    = (const float*)d_in[5];
    const float* bk    = (const float*)d_in[6];
    const float* Wv    = (const float*)d_in[7];
    const float* bv    = (const float*)d_in[8];
    const float* Wo    = (const float*)d_in[9];
    const float* bo    = (const float*)d_in[10];

    float* out = (float*)d_out;
    float* ave = out + (size_t)BB * SS * DD;

    cudaFuncSetAttribute(conv_mma, cudaFuncAttributeMaxDynamicSharedMemorySize, CV_SMEM);
    cudaFuncSetAttribute(scores_gemm, cudaFuncAttributeMaxDynamicSharedMemorySize, SG_SMEM);
    cudaFuncSetAttribute(softmax_ave, cudaFuncAttributeMaxDynamicSharedMemorySize, SMA_SMEM);
    cudaFuncSetAttribute(pv_mma, cudaFuncAttributeMaxDynamicSharedMemorySize, PV_SMEM);
    cudaFuncSetAttribute(proj_mma, cudaFuncAttributeMaxDynamicSharedMemorySize, CV_SMEM);

    xprep_kernel<<<dim3(SS / 128, BB, 3), 256>>>(query, key_t, value);
    wprep_kernel<<<dim3(DD / 64, 4), 256>>>(Wq, Wk, Wv, Wo);
    conv_mma<<<dim3(DD / 128, SS / 128, 3 * BB), 256, CV_SMEM>>>(bq, bk, bv);
    scores_gemm<<<dim3(64, HH, BB), 256, SG_SMEM>>>();
    softmax_ave<<<dim3(SS / 8, BB), 256, SMA_SMEM>>>(ave);
    pv_mma<<<dim3(SS / 128, HH, BB), 256, PV_SMEM>>>();
    proj_mma<<<dim3((BB * SS) / 128, DD / 128), 256, CV_SMEM>>>(bo, out);
}

// round 16
// speedup vs baseline: 1.0140x; 1.0140x over previous
#include <cuda_runtime.h>
#include <cuda_bf16.h>
#include <cstdint>

// ---------------------------------------------------------------------------
// ConvMultiheadAttention: B=8, S=1024, D=512, H=8, hd=64, KERNEL=3
// out  = [8,1024,512]  ; ave = [8,1024,1024]
// ---------------------------------------------------------------------------

#define BB 8
#define SS 1024
#define DD 512
#define HH 8
#define HD 64

typedef unsigned long long ull;

// ----- bf16 split helpers ----------------------------------------------------
__device__ __forceinline__ void bsplit2(float u, float v, uint32_t& ph, uint32_t& pl) {
    __nv_bfloat16 hu = __float2bfloat16_rn(u);
    __nv_bfloat16 hv = __float2bfloat16_rn(v);
    __nv_bfloat16 lu = __float2bfloat16_rn(u - __bfloat162float(hu));
    __nv_bfloat16 lv = __float2bfloat16_rn(v - __bfloat162float(hv));
    ph = (uint32_t)__bfloat16_as_ushort(hu) | ((uint32_t)__bfloat16_as_ushort(hv) << 16);
    pl = (uint32_t)__bfloat16_as_ushort(lu) | ((uint32_t)__bfloat16_as_ushort(lv) << 16);
}
__device__ __forceinline__ void mma_bf16s(float4& d, uint32_t a0, uint32_t a1,
                                          uint32_t a2, uint32_t a3,
                                          uint32_t b0, uint32_t b1) {
    asm("mma.sync.aligned.m16n8k16.row.col.f32.bf16.bf16.f32 "
        "{%0,%1,%2,%3}, {%4,%5,%6,%7}, {%8,%9}, {%0,%1,%2,%3};"
        : "+f"(d.x), "+f"(d.y), "+f"(d.z), "+f"(d.w)
        : "r"(a0), "r"(a1), "r"(a2), "r"(a3), "r"(b0), "r"(b1));
}
__device__ __forceinline__ void ldsm4(uint32_t& r0, uint32_t& r1, uint32_t& r2,
                                      uint32_t& r3, uint32_t addr) {
    asm volatile("ldmatrix.sync.aligned.m8n8.x4.shared.b16 {%0,%1,%2,%3}, [%4];"
        : "=r"(r0), "=r"(r1), "=r"(r2), "=r"(r3) : "r"(addr));
}

// ----- scratch (static device globals) --------------------------------------
// All packed arrays use PLAIN kpair order (ldmatrix supplies the fragment
// permutation in hardware).
__device__ uint32_t g_xh[3][BB][SS][256];    // inputs split hi
__device__ uint32_t g_xl[3][BB][SS][256];    // inputs split lo
__device__ uint32_t g_wh[4][3][DD][256];     // weights split hi, per tap (3=Wo)
__device__ uint32_t g_wl[4][3][DD][256];     // weights split lo
__device__ uint32_t g_sqh[BB * HH][SS][32];  // Q/64 split hi
__device__ uint32_t g_sql[BB * HH][SS][32];
__device__ uint32_t g_skh[BB * HH][SS][32];  // K split hi
__device__ uint32_t g_skl[BB * HH][SS][32];
__device__ float g_p[(size_t)BB * HH * SS * SS]; // raw scores
__device__ uint32_t g_ph[BB * HH][SS][512];  // probs split hi
__device__ uint32_t g_pl[BB * HH][SS][512];  // probs split lo
__device__ uint32_t g_vh[BB * HH][HD][512];  // V split hi
__device__ uint32_t g_vl[BB * HH][HD][512];  // V split lo
__device__ uint32_t g_oh[BB * SS][256];      // o1 split hi
__device__ uint32_t g_ol[BB * SS][256];      // o1 split lo

// ---------------------------------------------------------------------------
// Kernel 1: xprep — split inputs [B,S,D] into kpair-packed bf16 hi/lo (plain)
// ---------------------------------------------------------------------------
__global__ void xprep_kernel(const float* __restrict__ q,
                             const float* __restrict__ k,
                             const float* __restrict__ v) {
    const int tn = blockIdx.z, b = blockIdx.y, s0 = blockIdx.x * 128;
    const float* src = (tn == 0) ? q : (tn == 1) ? k : v;
    const int kp = threadIdx.x;             // 0..255
    for (int i = 0; i < 128; i++) {
        int s = s0 + i;
        float2 uv = *(const float2*)&src[((size_t)b * SS + s) * DD + 2 * kp];
        uint32_t ph, pl;
        bsplit2(uv.x, uv.y, ph, pl);
        g_xh[tn][b][s][kp] = ph;
        g_xl[tn][b][s][kp] = pl;
    }
}

// ---------------------------------------------------------------------------
// Kernel 2: wprep — split weights (Wq/Wk/Wv per tap, Wo) into plain hi/lo.
// ---------------------------------------------------------------------------
__global__ void wprep_kernel(const float* __restrict__ Wq,
                             const float* __restrict__ Wk,
                             const float* __restrict__ Wv,
                             const float* __restrict__ Wo) {
    const int tn = blockIdx.y;
    const float* W = (tn == 0) ? Wq : (tn == 1) ? Wk : (tn == 2) ? Wv : Wo;
    const int KER = (tn == 0 || tn == 1) ? 3 : 1;
    const int Kdim = DD * KER;
    const int co0 = blockIdx.x * 64;
    const int kp = threadIdx.x;              // 0..255 (ci pair)
    for (int tap = 0; tap < KER; tap++)
        for (int i = 0; i < 64; i++) {
            int co = co0 + i;
            float u = W[(size_t)co * Kdim + (2 * kp) * KER + tap];
            float vv = W[(size_t)co * Kdim + (2 * kp + 1) * KER + tap];
            uint32_t ph, pl;
            bsplit2(u, vv, ph, pl);
            g_wh[tn][tap][co][kp] = ph;
            g_wl[tn][tap][co][kp] = pl;
        }
}

// ---------------------------------------------------------------------------
// Kernel 3: conv1d as tap-decomposed bf16 MMA GEMM (split, 3 terms), LDSM
// fragment loads. Epilogues emit packed bf16 hi/lo directly:
//   Q/K: smem-staged [s][d] transpose -> coalesced 128B packed row writes
//   V:   s-kpairs (adjacent cols in-thread) -> g_vh/g_vl
// No fp32 intermediate; qkprep deleted.
// ---------------------------------------------------------------------------
#define CV_ST 20
#define CV_AH 0
#define CV_AL 2560
#define CV_BH 5120
#define CV_BL 7680
#define CV_BUF_U32 10240
#define CV_SMEM (2 * CV_BUF_U32 * (int)sizeof(uint32_t))

__global__ __launch_bounds__(256, 2)
void conv_mma(const float* __restrict__ bq, const float* __restrict__ bk,
              const float* __restrict__ bv) {
    extern __shared__ uint32_t smu[];
    __shared__ float s_bias[128];

    const int zz = blockIdx.z, tn = zz / BB, b = zz % BB;
    const float* bias = (tn == 0) ? bq : (tn == 1) ? bk : bv;
    const int KER = (tn == 2) ? 1 : 3;
    const int pad = KER >> 1;
    const int NIT = KER * 16;
    const int m0 = blockIdx.x * 128, n0 = blockIdx.y * 128;
    const int tid = threadIdx.x, wid = tid >> 5, lane = tid & 31;
    const int g = lane >> 2, tg = lane & 3;
    const int wm = (wid >> 2) * 64, wn = (wid & 3) * 32;
    const int lt = lane >> 3, ro = lane & 7;   // ldsm tile index, row offset

    if (tid < 128) s_bias[tid] = bias[m0 + tid];

    const uint32_t sbase = (uint32_t)__cvta_generic_to_shared(smu);

    float4 dacc[4][4];
    #pragma unroll
    for (int mi = 0; mi < 4; mi++)
        #pragma unroll
        for (int ni = 0; ni < 4; ni++) dacc[mi][ni] = make_float4(0.f, 0.f, 0.f, 0.f);

    const int a_row = tid >> 1, a_half = (tid & 1) * 8;
    const int b_s = tid & 127, b_half = (tid >> 7) * 8;

    uint4 rah0, rah1, ral0, ral1, rbh0, rbh1, rbl0, rbl1;

    auto ldg_slab = [&](int it) {
        int tap = it >> 4, c = it & 15;
        const uint32_t* wh = &g_wh[tn][tap][m0 + a_row][c * 16 + a_half];
        const uint32_t* wl = &g_wl[tn][tap][m0 + a_row][c * 16 + a_half];
        rah0 = *(const uint4*)&wh[0]; rah1 = *(const uint4*)&wh[4];
        ral0 = *(const uint4*)&wl[0]; ral1 = *(const uint4*)&wl[4];
        int s_glob = n0 + b_s + tap - pad;
        if ((unsigned)s_glob < (unsigned)SS) {
            const uint32_t* xh = &g_xh[tn][b][s_glob][c * 16 + b_half];
            const uint32_t* xl = &g_xl[tn][b][s_glob][c * 16 + b_half];
            rbh0 = *(const uint4*)&xh[0]; rbh1 = *(const uint4*)&xh[4];
            rbl0 = *(const uint4*)&xl[0]; rbl1 = *(const uint4*)&xl[4];
        } else {
            rbh0 = make_uint4(0, 0, 0, 0); rbh1 = rbh0;
            rbl0 = rbh0; rbl1 = rbh0;
        }
    };
    auto sts_slab = [&](int bf) {
        uint32_t* Ah = smu + bf * CV_BUF_U32 + CV_AH + a_row * CV_ST + a_half;
        uint32_t* Al = smu + bf * CV_BUF_U32 + CV_AL + a_row * CV_ST + a_half;
        uint32_t* Bh = smu + bf * CV_BUF_U32 + CV_BH + b_s * CV_ST + b_half;
        uint32_t* Bl = smu + bf * CV_BUF_U32 + CV_BL + b_s * CV_ST + b_half;
        *(uint4*)&Ah[0] = rah0; *(uint4*)&Ah[4] = rah1;
        *(uint4*)&Al[0] = ral0; *(uint4*)&Al[4] = ral1;
        *(uint4*)&Bh[0] = rbh0; *(uint4*)&Bh[4] = rbh1;
        *(uint4*)&Bl[0] = rbl0; *(uint4*)&Bl[4] = rbl1;
    };

    ldg_slab(0);
    sts_slab(0);
    __syncthreads();

    for (int it = 0; it < NIT; it++) {
        const int bf = it & 1;
        const bool have = (it + 1) < NIT;
        if (have) ldg_slab(it + 1);

        const uint32_t bufB = sbase + 4 * (bf * CV_BUF_U32);
        #pragma unroll
        for (int s = 0; s < 2; s++) {
            uint32_t bh[4][2], bl[4][2];
            #pragma unroll
            for (int p = 0; p < 2; p++) {
                uint32_t off = (wn + (2 * p + (lt >> 1)) * 8 + ro) * CV_ST
                             + s * 8 + (lt & 1) * 4;
                uint32_t r0, r1, r2, r3;
                ldsm4(r0, r1, r2, r3, bufB + 4 * (CV_BH + off));
                bh[2 * p][0] = r0; bh[2 * p][1] = r1;
                bh[2 * p + 1][0] = r2; bh[2 * p + 1][1] = r3;
                ldsm4(r0, r1, r2, r3, bufB + 4 * (CV_BL + off));
                bl[2 * p][0] = r0; bl[2 * p][1] = r1;
                bl[2 * p + 1][0] = r2; bl[2 * p + 1][1] = r3;
            }
            #pragma unroll
            for (int mi = 0; mi < 4; mi++) {
                uint32_t aoff = (wm + mi * 16 + (lt & 1) * 8 + ro) * CV_ST
                              + s * 8 + (lt >> 1) * 4;
                uint32_t a0, a1, a2, a3, l0, l1, l2, l3;
                ldsm4(a0, a1, a2, a3, bufB + 4 * (CV_AH + aoff));
                ldsm4(l0, l1, l2, l3, bufB + 4 * (CV_AL + aoff));
                #pragma unroll
                for (int ni = 0; ni < 4; ni++) {
                    mma_bf16s(dacc[mi][ni], a0, a1, a2, a3, bh[ni][0], bh[ni][1]);
                    mma_bf16s(dacc[mi][ni], a0, a1, a2, a3, bl[ni][0], bl[ni][1]);
                    mma_bf16s(dacc[mi][ni], l0, l1, l2, l3, bh[ni][0], bh[ni][1]);
                }
            }
        }

        if (have) sts_slab(bf ^ 1);
        __syncthreads();
    }

    if (tn != 2) {
        // Q/K: stage transposed [s][d] fp32 in smem (stride 132), then each
        // lane packs 8 contiguous d-kpairs of one s-row -> coalesced writes.
        float* st = (float*)smu;
        const float scale = (tn == 0) ? 0.015625f : 1.0f;
        #pragma unroll
        for (int mi = 0; mi < 4; mi++) {
            int r = wm + mi * 16 + g;
            float b0 = s_bias[r], b1 = s_bias[r + 8];
            #pragma unroll
            for (int ni = 0; ni < 4; ni++) {
                int col = wn + ni * 8 + 2 * tg;
                float4 d = dacc[mi][ni];
                st[col * 132 + r]           = (d.x + b0) * scale;
                st[(col + 1) * 132 + r]     = (d.y + b0) * scale;
                st[col * 132 + r + 8]       = (d.z + b1) * scale;
                st[(col + 1) * 132 + r + 8] = (d.w + b1) * scale;
            }
        }
        __syncthreads();

        uint32_t (*dsth)[SS][32] = (tn == 0) ? g_sqh : g_skh;
        uint32_t (*dstl)[SS][32] = (tn == 0) ? g_sql : g_skl;
        const int c8 = lane & 7, rr4 = lane >> 3;
        #pragma unroll
        for (int pass = 0; pass < 4; pass++) {
            int sl = pass * 32 + wid * 4 + rr4;
            int sg = n0 + sl;
            int bh = b * HH + (m0 >> 6) + (c8 >> 2);
            int kp0 = (c8 & 3) * 8;
            uint32_t hbuf[8], lbuf[8];
            #pragma unroll
            for (int j = 0; j < 8; j++) {
                float u = st[sl * 132 + c8 * 16 + 2 * j];
                float v = st[sl * 132 + c8 * 16 + 2 * j + 1];
                bsplit2(u, v, hbuf[j], lbuf[j]);
            }
            *(uint4*)&dsth[bh][sg][kp0]     = *(uint4*)&hbuf[0];
            *(uint4*)&dsth[bh][sg][kp0 + 4] = *(uint4*)&hbuf[4];
            *(uint4*)&dstl[bh][sg][kp0]     = *(uint4*)&lbuf[0];
            *(uint4*)&dstl[bh][sg][kp0 + 4] = *(uint4*)&lbuf[4];
        }
    } else {
        // V: emit packed bf16 hi/lo directly (kpair over s = adjacent cols)
        #pragma unroll
        for (int mi = 0; mi < 4; mi++) {
            int lr0 = wm + mi * 16 + g;
            float b0 = s_bias[lr0], b1 = s_bias[lr0 + 8];
            int row0 = m0 + lr0, row1 = row0 + 8;
            int bh0 = b * HH + (row0 >> 6), bh1 = b * HH + (row1 >> 6);
            int dd0 = row0 & 63, dd1 = row1 & 63;
            #pragma unroll
            for (int ni = 0; ni < 4; ni++) {
                int kp = (n0 + wn + ni * 8 + 2 * tg) >> 1;
                float4 d = dacc[mi][ni];
                uint32_t ph, pl;
                bsplit2(d.x + b0, d.y + b0, ph, pl);
                g_vh[bh0][dd0][kp] = ph; g_vl[bh0][dd0][kp] = pl;
                bsplit2(d.z + b1, d.w + b1, ph, pl);
                g_vh[bh1][dd1][kp] = ph; g_vl[bh1][dd1][kp] = pl;
            }
        }
    }
}

// ---------------------------------------------------------------------------
// Kernel 4: scores GEMM via bf16 mma (3 terms), LDSM fragment loads.
// smem stride 36 u32. Raw scores -> g_p.
// ---------------------------------------------------------------------------
#define SG_ST 36
#define SG_A_H 0
#define SG_A_L 4608
#define SG_B_H 9216
#define SG_B_L 13824
#define SG_SMEM (18432 * (int)sizeof(uint32_t))

__global__ __launch_bounds__(256, 2) void scores_gemm() {
    extern __shared__ uint32_t smu[];
    const int b = blockIdx.z, h = blockIdx.y;
    const int s0 = (blockIdx.x >> 3) * 128, t0 = (blockIdx.x & 7) * 128;
    const int bh = b * HH + h;
    const int tid = threadIdx.x, wid = tid >> 5, lane = tid & 31;
    const int g = lane >> 2, tg = lane & 3;
    const int wm = (wid >> 2) * 64, wn = (wid & 3) * 32;
    const int lt = lane >> 3, ro = lane & 7;

    const uint32_t sbase = (uint32_t)__cvta_generic_to_shared(smu);

    {
        const int row = tid >> 1, c0 = (tid & 1) * 16;
        const uint32_t* sa_h = &g_sqh[bh][s0 + row][c0];
        const uint32_t* sa_l = &g_sql[bh][s0 + row][c0];
        const uint32_t* sb_h = &g_skh[bh][t0 + row][c0];
        const uint32_t* sb_l = &g_skl[bh][t0 + row][c0];
        uint32_t* Ah = smu + SG_A_H + row * SG_ST + c0;
        uint32_t* Al = smu + SG_A_L + row * SG_ST + c0;
        uint32_t* Bh = smu + SG_B_H + row * SG_ST + c0;
        uint32_t* Bl = smu + SG_B_L + row * SG_ST + c0;
        #pragma unroll
        for (int i = 0; i < 4; i++) {
            *(uint4*)&Ah[4 * i] = *(const uint4*)&sa_h[4 * i];
            *(uint4*)&Al[4 * i] = *(const uint4*)&sa_l[4 * i];
            *(uint4*)&Bh[4 * i] = *(const uint4*)&sb_h[4 * i];
            *(uint4*)&Bl[4 * i] = *(const uint4*)&sb_l[4 * i];
        }
    }
    __syncthreads();

    float4 dacc[4][4];
    #pragma unroll
    for (int mi = 0; mi < 4; mi++)
        #pragma unroll
        for (int ni = 0; ni < 4; ni++) dacc[mi][ni] = make_float4(0.f, 0.f, 0.f, 0.f);

    #pragma unroll
    for (int s = 0; s < 4; s++) {
        uint32_t bh2[4][2], bl2[4][2];
        #pragma unroll
        for (int p = 0; p < 2; p++) {
            uint32_t off = (wn + (2 * p + (lt >> 1)) * 8 + ro) * SG_ST
                         + s * 8 + (lt & 1) * 4;
            uint32_t r0, r1, r2, r3;
            ldsm4(r0, r1, r2, r3, sbase + 4 * (SG_B_H + off));
            bh2[2 * p][0] = r0; bh2[2 * p][1] = r1;
            bh2[2 * p + 1][0] = r2; bh2[2 * p + 1][1] = r3;
            ldsm4(r0, r1, r2, r3, sbase + 4 * (SG_B_L + off));
            bl2[2 * p][0] = r0; bl2[2 * p][1] = r1;
            bl2[2 * p + 1][0] = r2; bl2[2 * p + 1][1] = r3;
        }
        #pragma unroll
        for (int mi = 0; mi < 4; mi++) {
            uint32_t aoff = (wm + mi * 16 + (lt & 1) * 8 + ro) * SG_ST
                          + s * 8 + (lt >> 1) * 4;
            uint32_t a0, a1, a2, a3, l0, l1, l2, l3;
            ldsm4(a0, a1, a2, a3, sbase + 4 * (SG_A_H + aoff));
            ldsm4(l0, l1, l2, l3, sbase + 4 * (SG_A_L + aoff));
            #pragma unroll
            for (int ni = 0; ni < 4; ni++) {
                mma_bf16s(dacc[mi][ni], a0, a1, a2, a3, bh2[ni][0], bh2[ni][1]);
                mma_bf16s(dacc[mi][ni], a0, a1, a2, a3, bl2[ni][0], bl2[ni][1]);
                mma_bf16s(dacc[mi][ni], l0, l1, l2, l3, bh2[ni][0], bh2[ni][1]);
            }
        }
    }

    float* Pg = &g_p[((size_t)bh << 20)];
    #pragma unroll
    for (int mi = 0; mi < 4; mi++) {
        int lr0 = s0 + wm + mi * 16 + g;
        #pragma unroll
        for (int ni = 0; ni < 4; ni++) {
            int col = t0 + wn + ni * 8 + 2 * tg;
            float4 d = dacc[mi][ni];
            *(float2*)&Pg[(size_t)lr0 * SS + col]       = make_float2(d.x, d.y);
            *(float2*)&Pg[(size_t)(lr0 + 8) * SS + col] = make_float2(d.z, d.w);
        }
    }
}

// ---------------------------------------------------------------------------
// Kernel 5: softmax + fused ave + plain packed bf16 split P emission.
// ---------------------------------------------------------------------------
#define SMA_SMEM (16384 * (int)sizeof(float))

__global__ __launch_bounds__(256) void softmax_ave(float* __restrict__ ave) {
    extern __shared__ float smf[];
    float* buf = smf;            // 8*1024
    float* av  = smf + 8192;     // 8*1024

    const int b = blockIdx.y, s0 = blockIdx.x * 8;
    const int tid = threadIdx.x, w = tid >> 5, lane = tid & 31;

    #pragma unroll
    for (int i = 0; i < 8; i++)
        *(float4*)&av[(i * 256 + tid) * 4] = make_float4(0.f, 0.f, 0.f, 0.f);

    for (int h = 0; h < HH; h++) {
        const int bh = b * HH + h;
        const float* Pg = &g_p[(((size_t)bh) << 20) + (size_t)s0 * SS];
        __syncthreads();
        #pragma unroll
        for (int i = 0; i < 8; i++) {
            int off = (i * 256 + tid) * 4;
            *(float4*)&buf[off] = *(const float4*)&Pg[off];
        }
        __syncthreads();

        {
            float* row = &buf[w * 1024];
            float* arow = &av[w * 1024];
            float m = -1e30f;
            for (int j = lane; j < 1024; j += 32) m = fmaxf(m, row[j]);
            #pragma unroll
            for (int o = 16; o > 0; o >>= 1)
                m = fmaxf(m, __shfl_xor_sync(0xffffffffu, m, o));
            float s = 0.0f;
            for (int j = lane; j < 1024; j += 32) {
                float e = __expf(row[j] - m);
                row[j] = e;
                s += e;
            }
            #pragma unroll
            for (int o = 16; o > 0; o >>= 1) s += __shfl_xor_sync(0xffffffffu, s, o);
            float inv = 1.0f / s;
            for (int j = lane; j < 1024; j += 32) {
                float p = row[j] * inv;
                row[j] = p;
                arow[j] += 0.125f * p;
            }
        }
        __syncthreads();

        #pragma unroll
        for (int i = 0; i < 16; i++) {
            int tt = i * 256 + tid;          // 0..4095
            int r = tt >> 9, kk = tt & 511;
            float2 uv = *(float2*)&buf[r * 1024 + 2 * kk];
            uint32_t ph, pl;
            bsplit2(uv.x, uv.y, ph, pl);
            g_ph[bh][s0 + r][kk] = ph;
            g_pl[bh][s0 + r][kk] = pl;
        }
    }

    __syncthreads();
    #pragma unroll
    for (int i = 0; i < 8; i++) {
        int off = (i * 256 + tid) * 4;
        int r = off >> 10, c = off & 1023;
        *(float4*)&ave[((size_t)b * SS + s0 + r) * SS + c] = *(float4*)&av[off];
    }
}

// ---------------------------------------------------------------------------
// Kernel 6: PV GEMM via bf16 mma (3 terms), LDSM fragment loads.
// smem stride 20 u32. Epilogue emits plain packed o1.
// ---------------------------------------------------------------------------
#define PV_ST 20
#define PV_A_H 0
#define PV_A_L 2560
#define PV_B_H 5120
#define PV_B_L 6400
#define PV_BUF_U32 7680
#define PV_SMEM (2 * PV_BUF_U32 * (int)sizeof(uint32_t))

__global__ __launch_bounds__(256, 2) void pv_mma() {
    extern __shared__ uint32_t smu[];
    const int b = blockIdx.z, h = blockIdx.y, s0 = blockIdx.x * 128;
    const int bh = b * HH + h;
    const int tid = threadIdx.x, wid = tid >> 5, lane = tid & 31;
    const int g = lane >> 2, tg = lane & 3;
    const int wm = (wid >> 2) * 64, wn = (wid & 3) * 16;
    const int lt = lane >> 3, ro = lane & 7;

    const uint32_t sbase = (uint32_t)__cvta_generic_to_shared(smu);

    float4 dacc[4][2];
    #pragma unroll
    for (int mi = 0; mi < 4; mi++)
        #pragma unroll
        for (int ni = 0; ni < 2; ni++) dacc[mi][ni] = make_float4(0.f, 0.f, 0.f, 0.f);

    const int a_row = tid >> 1, a_c0 = (tid & 1) * 8;
    const int b_d = tid >> 2, b_c0 = (tid & 3) * 4;

    uint4 rah0, rah1, ral0, ral1, rbh, rbl;

    auto ldg_slab = [&](int c) {
        const uint32_t* ph = &g_ph[bh][s0 + a_row][c * 16 + a_c0];
        const uint32_t* pl = &g_pl[bh][s0 + a_row][c * 16 + a_c0];
        rah0 = *(const uint4*)&ph[0]; rah1 = *(const uint4*)&ph[4];
        ral0 = *(const uint4*)&pl[0]; ral1 = *(const uint4*)&pl[4];
        rbh = *(const uint4*)&g_vh[bh][b_d][c * 16 + b_c0];
        rbl = *(const uint4*)&g_vl[bh][b_d][c * 16 + b_c0];
    };
    auto sts_slab = [&](int bf) {
        uint32_t* Ah = smu + bf * PV_BUF_U32 + PV_A_H + a_row * PV_ST + a_c0;
        uint32_t* Al = smu + bf * PV_BUF_U32 + PV_A_L + a_row * PV_ST + a_c0;
        uint32_t* Bh = smu + bf * PV_BUF_U32 + PV_B_H + b_d * PV_ST + b_c0;
        uint32_t* Bl = smu + bf * PV_BUF_U32 + PV_B_L + b_d * PV_ST + b_c0;
        *(uint4*)&Ah[0] = rah0; *(uint4*)&Ah[4] = rah1;
        *(uint4*)&Al[0] = ral0; *(uint4*)&Al[4] = ral1;
        *(uint4*)&Bh[0] = rbh;
        *(uint4*)&Bl[0] = rbl;
    };

    ldg_slab(0);
    sts_slab(0);
    __syncthreads();

    for (int c = 0; c < 32; c++) {
        const int bf = c & 1;
        const bool have = (c + 1) < 32;
        if (have) ldg_slab(c + 1);

        const uint32_t bufB = sbase + 4 * (bf * PV_BUF_U32);
        #pragma unroll
        for (int s = 0; s < 2; s++) {
            uint32_t bh2[2][2], bl2[2][2];
            {
                uint32_t off = (wn + (lt >> 1) * 8 + ro) * PV_ST
                             + s * 8 + (lt & 1) * 4;
                uint32_t r0, r1, r2, r3;
                ldsm4(r0, r1, r2, r3, bufB + 4 * (PV_B_H + off));
                bh2[0][0] = r0; bh2[0][1] = r1; bh2[1][0] = r2; bh2[1][1] = r3;
                ldsm4(r0, r1, r2, r3, bufB + 4 * (PV_B_L + off));
                bl2[0][0] = r0; bl2[0][1] = r1; bl2[1][0] = r2; bl2[1][1] = r3;
            }
            #pragma unroll
            for (int mi = 0; mi < 4; mi++) {
                uint32_t aoff = (wm + mi * 16 + (lt & 1) * 8 + ro) * PV_ST
                              + s * 8 + (lt >> 1) * 4;
                uint32_t a0, a1, a2, a3, l0, l1, l2, l3;
                ldsm4(a0, a1, a2, a3, bufB + 4 * (PV_A_H + aoff));
                ldsm4(l0, l1, l2, l3, bufB + 4 * (PV_A_L + aoff));
                #pragma unroll
                for (int ni = 0; ni < 2; ni++) {
                    mma_bf16s(dacc[mi][ni], a0, a1, a2, a3, bh2[ni][0], bh2[ni][1]);
                    mma_bf16s(dacc[mi][ni], a0, a1, a2, a3, bl2[ni][0], bl2[ni][1]);
                    mma_bf16s(dacc[mi][ni], l0, l1, l2, l3, bh2[ni][0], bh2[ni][1]);
                }
            }
        }

        if (have) sts_slab(bf ^ 1);
        __syncthreads();
    }

    // epilogue: pack (col, col+1) pairs = one kpair over d (plain order)
    #pragma unroll
    for (int mi = 0; mi < 4; mi++) {
        int lr0 = s0 + wm + mi * 16 + g;
        int row0 = b * SS + lr0, row1 = row0 + 8;
        #pragma unroll
        for (int ni = 0; ni < 2; ni++) {
            int kp = (h * HD + wn + ni * 8 + 2 * tg) >> 1;
            float4 d = dacc[mi][ni];
            uint32_t ph, pl;
            bsplit2(d.x, d.y, ph, pl);
            g_oh[row0][kp] = ph; g_ol[row0][kp] = pl;
            bsplit2(d.z, d.w, ph, pl);
            g_oh[row1][kp] = ph; g_ol[row1][kp] = pl;
        }
    }
}

// ---------------------------------------------------------------------------
// Kernel 7: output projection via bf16 mma (3 terms), LDSM fragment loads.
// ---------------------------------------------------------------------------
__global__ __launch_bounds__(256, 2) void proj_mma(const float* __restrict__ bo,
                                                   float* __restrict__ out) {
    extern __shared__ uint32_t smu[];
    const int m0 = blockIdx.x * 128, n0 = blockIdx.y * 128;
    const int tid = threadIdx.x, wid = tid >> 5, lane = tid & 31;
    const int g = lane >> 2, tg = lane & 3;
    const int wm = (wid >> 2) * 64, wn = (wid & 3) * 32;
    const int lt = lane >> 3, ro = lane & 7;

    const uint32_t sbase = (uint32_t)__cvta_generic_to_shared(smu);

    float4 dacc[4][4];
    #pragma unroll
    for (int mi = 0; mi < 4; mi++)
        #pragma unroll
        for (int ni = 0; ni < 4; ni++) dacc[mi][ni] = make_float4(0.f, 0.f, 0.f, 0.f);

    const int a_row = tid >> 1, a_half = (tid & 1) * 8;

    uint4 rah0, rah1, ral0, ral1, rbh0, rbh1, rbl0, rbl1;

    auto ldg_slab = [&](int c) {
        const uint32_t* oh = &g_oh[m0 + a_row][c * 16 + a_half];
        const uint32_t* ol = &g_ol[m0 + a_row][c * 16 + a_half];
        rah0 = *(const uint4*)&oh[0]; rah1 = *(const uint4*)&oh[4];
        ral0 = *(const uint4*)&ol[0]; ral1 = *(const uint4*)&ol[4];
        const uint32_t* wh = &g_wh[3][0][n0 + a_row][c * 16 + a_half];
        const uint32_t* wl = &g_wl[3][0][n0 + a_row][c * 16 + a_half];
        rbh0 = *(const uint4*)&wh[0]; rbh1 = *(const uint4*)&wh[4];
        rbl0 = *(const uint4*)&wl[0]; rbl1 = *(const uint4*)&wl[4];
    };
    auto sts_slab = [&](int bf) {
        uint32_t* Ah = smu + bf * CV_BUF_U32 + CV_AH + a_row * CV_ST + a_half;
        uint32_t* Al = smu + bf * CV_BUF_U32 + CV_AL + a_row * CV_ST + a_half;
        uint32_t* Bh = smu + bf * CV_BUF_U32 + CV_BH + a_row * CV_ST + a_half;
        uint32_t* Bl = smu + bf * CV_BUF_U32 + CV_BL + a_row * CV_ST + a_half;
        *(uint4*)&Ah[0] = rah0; *(uint4*)&Ah[4] = rah1;
        *(uint4*)&Al[0] = ral0; *(uint4*)&Al[4] = ral1;
        *(uint4*)&Bh[0] = rbh0; *(uint4*)&Bh[4] = rbh1;
        *(uint4*)&Bl[0] = rbl0; *(uint4*)&Bl[4] = rbl1;
    };

    ldg_slab(0);
    sts_slab(0);
    __syncthreads();

    for (int c = 0; c < 16; c++) {
        const int bf = c & 1;
        const bool have = (c + 1) < 16;
        if (have) ldg_slab(c + 1);

        const uint32_t bufB = sbase + 4 * (bf * CV_BUF_U32);
        #pragma unroll
        for (int s = 0; s < 2; s++) {
            uint32_t bh[4][2], bl[4][2];
            #pragma unroll
            for (int p = 0; p < 2; p++) {
                uint32_t off = (wn + (2 * p + (lt >> 1)) * 8 + ro) * CV_ST
                             + s * 8 + (lt & 1) * 4;
                uint32_t r0, r1, r2, r3;
                ldsm4(r0, r1, r2, r3, bufB + 4 * (CV_BH + off));
                bh[2 * p][0] = r0; bh[2 * p][1] = r1;
                bh[2 * p + 1][0] = r2; bh[2 * p + 1][1] = r3;
                ldsm4(r0, r1, r2, r3, bufB + 4 * (CV_BL + off));
                bl[2 * p][0] = r0; bl[2 * p][1] = r1;
                bl[2 * p + 1][0] = r2; bl[2 * p + 1][1] = r3;
            }
            #pragma unroll
            for (int mi = 0; mi < 4; mi++) {
                uint32_t aoff = (wm + mi * 16 + (lt & 1) * 8 + ro) * CV_ST
                              + s * 8 + (lt >> 1) * 4;
                uint32_t a0, a1, a2, a3, l0, l1, l2, l3;
                ldsm4(a0, a1, a2, a3, bufB + 4 * (CV_AH + aoff));
                ldsm4(l0, l1, l2, l3, bufB + 4 * (CV_AL + aoff));
                #pragma unroll
                for (int ni = 0; ni < 4; ni++) {
                    mma_bf16s(dacc[mi][ni], a0, a1, a2, a3, bh[ni][0], bh[ni][1]);
                    mma_bf16s(dacc[mi][ni], a0, a1, a2, a3, bl[ni][0], bl[ni][1]);
                    mma_bf16s(dacc[mi][ni], l0, l1, l2, l3, bh[ni][0], bh[ni][1]);
                }
            }
        }

        if (have) sts_slab(bf ^ 1);
        __syncthreads();
    }

    #pragma unroll
    for (int mi = 0; mi < 4; mi++) {
        int lr0 = m0 + wm + mi * 16 + g;
        #pragma unroll
        for (int ni = 0; ni < 4; ni++) {
            int col = n0 + wn + ni * 8 + 2 * tg;
            float2 bb = *(const float2*)&bo[col];
            float4 d = dacc[mi][ni];
            *(float2*)&out[(size_t)lr0 * DD + col]       = make_float2(d.x + bb.x, d.y + bb.y);
            *(float2*)&out[(size_t)(lr0 + 8) * DD + col] = make_float2(d.z + bb.x, d.w + bb.y);
        }
    }
}

// ---------------------------------------------------------------------------
extern "C" void kernel_launch(void* const* d_in, const int* in_sizes, int n_in,
                              void* d_out, int out_size) {
    const float* query = (const float*)d_in[0];
    const float* key_t = (const float*)d_in[1];
    const float* value = (const float*)d_in[2];
    const float* Wq    = (const float*)d_in[3];
    const float* bq    = (const float*)d_in[4];
    const float* Wk    = (const float*)d_in[5];
    const float* bk    = (const float*)d_in[6];
    const float* Wv    = (const float*)d_in[7];
    const float* bv    = (const float*)d_in[8];
    const float* Wo    = (const float*)d_in[9];
    const float* bo    = (const float*)d_in[10];

    float* out = (float*)d_out;
    float* ave = out + (size_t)BB * SS * DD;

    cudaFuncSetAttribute(conv_mma, cudaFuncAttributeMaxDynamicSharedMemorySize, CV_SMEM);
    cudaFuncSetAttribute(scores_gemm, cudaFuncAttributeMaxDynamicSharedMemorySize, SG_SMEM);
    cudaFuncSetAttribute(softmax_ave, cudaFuncAttributeMaxDynamicSharedMemorySize, SMA_SMEM);
    cudaFuncSetAttribute(pv_mma, cudaFuncAttributeMaxDynamicSharedMemorySize, PV_SMEM);
    cudaFuncSetAttribute(proj_mma, cudaFuncAttributeMaxDynamicSharedMemorySize, CV_SMEM);

    xprep_kernel<<<dim3(SS / 128, BB, 3), 256>>>(query, key_t, value);
    wprep_kernel<<<dim3(DD / 64, 4), 256>>>(Wq, Wk, Wv, Wo);
    conv_mma<<<dim3(DD / 128, SS / 128, 3 * BB), 256, CV_SMEM>>>(bq, bk, bv);
    scores_gemm<<<dim3(64, HH, BB), 256, SG_SMEM>>>();
    softmax_ave<<<dim3(SS / 8, BB), 256, SMA_SMEM>>>(ave);
    pv_mma<<<dim3(SS / 128, HH, BB), 256, PV_SMEM>>>();
    proj_mma<<<dim3((BB * SS) / 128, DD / 128), 256, CV_SMEM>>>(bo, out);
}

// round 17
// speedup vs baseline: 1.0367x; 1.0224x over previous
#include <cuda_runtime.h>
#include <cuda_bf16.h>
#include <cstdint>

// ---------------------------------------------------------------------------
// ConvMultiheadAttention: B=8, S=1024, D=512, H=8, hd=64, KERNEL=3
// out  = [8,1024,512]  ; ave = [8,1024,1024]
// ---------------------------------------------------------------------------

#define BB 8
#define SS 1024
#define DD 512
#define HH 8
#define HD 64

typedef unsigned long long ull;

// ----- bf16 split helpers ----------------------------------------------------
__device__ __forceinline__ void bsplit2(float u, float v, uint32_t& ph, uint32_t& pl) {
    __nv_bfloat16 hu = __float2bfloat16_rn(u);
    __nv_bfloat16 hv = __float2bfloat16_rn(v);
    __nv_bfloat16 lu = __float2bfloat16_rn(u - __bfloat162float(hu));
    __nv_bfloat16 lv = __float2bfloat16_rn(v - __bfloat162float(hv));
    ph = (uint32_t)__bfloat16_as_ushort(hu) | ((uint32_t)__bfloat16_as_ushort(hv) << 16);
    pl = (uint32_t)__bfloat16_as_ushort(lu) | ((uint32_t)__bfloat16_as_ushort(lv) << 16);
}
__device__ __forceinline__ void mma_bf16s(float4& d, uint32_t a0, uint32_t a1,
                                          uint32_t a2, uint32_t a3,
                                          uint32_t b0, uint32_t b1) {
    asm("mma.sync.aligned.m16n8k16.row.col.f32.bf16.bf16.f32 "
        "{%0,%1,%2,%3}, {%4,%5,%6,%7}, {%8,%9}, {%0,%1,%2,%3};"
        : "+f"(d.x), "+f"(d.y), "+f"(d.z), "+f"(d.w)
        : "r"(a0), "r"(a1), "r"(a2), "r"(a3), "r"(b0), "r"(b1));
}
__device__ __forceinline__ void ldsm4(uint32_t& r0, uint32_t& r1, uint32_t& r2,
                                      uint32_t& r3, uint32_t addr) {
    asm volatile("ldmatrix.sync.aligned.m8n8.x4.shared.b16 {%0,%1,%2,%3}, [%4];"
        : "=r"(r0), "=r"(r1), "=r"(r2), "=r"(r3) : "r"(addr));
}
// kpair position permutation used by qkprep (pos32 layout, LDSM-free consumer
// staging is plain; scores LDSM handles fragment permutation, so plain order)
__device__ __forceinline__ int pos16(int kp) { return (kp & 3) * 4 + (kp >> 2); }

// ----- scratch (static device globals) --------------------------------------
__device__ float g_qkv[2][BB][DD][SS];       // conv outputs Q,K [B,D,S]
__device__ uint32_t g_xh[3][BB][SS][256];    // inputs split hi
__device__ uint32_t g_xl[3][BB][SS][256];    // inputs split lo
__device__ uint32_t g_wh[4][3][DD][256];     // weights split hi, per tap (3=Wo)
__device__ uint32_t g_wl[4][3][DD][256];     // weights split lo
__device__ uint32_t g_sqh[BB * HH][SS][32];  // Q/64 split hi
__device__ uint32_t g_sql[BB * HH][SS][32];
__device__ uint32_t g_skh[BB * HH][SS][32];  // K split hi
__device__ uint32_t g_skl[BB * HH][SS][32];
__device__ float g_p[(size_t)BB * HH * SS * SS]; // raw scores
__device__ uint32_t g_ph[BB * HH][SS][512];  // probs split hi
__device__ uint32_t g_pl[BB * HH][SS][512];  // probs split lo
__device__ uint32_t g_vh[BB * HH][HD][512];  // V split hi
__device__ uint32_t g_vl[BB * HH][HD][512];  // V split lo
__device__ uint32_t g_oh[BB * SS][256];      // o1 split hi
__device__ uint32_t g_ol[BB * SS][256];      // o1 split lo

// ---------------------------------------------------------------------------
// Kernel 1: xprep — split inputs [B,S,D] into kpair-packed bf16 hi/lo (plain)
// ---------------------------------------------------------------------------
__global__ void xprep_kernel(const float* __restrict__ q,
                             const float* __restrict__ k,
                             const float* __restrict__ v) {
    const int tn = blockIdx.z, b = blockIdx.y, s0 = blockIdx.x * 128;
    const float* src = (tn == 0) ? q : (tn == 1) ? k : v;
    const int kp = threadIdx.x;             // 0..255
    for (int i = 0; i < 128; i++) {
        int s = s0 + i;
        float2 uv = *(const float2*)&src[((size_t)b * SS + s) * DD + 2 * kp];
        uint32_t ph, pl;
        bsplit2(uv.x, uv.y, ph, pl);
        g_xh[tn][b][s][kp] = ph;
        g_xl[tn][b][s][kp] = pl;
    }
}

// ---------------------------------------------------------------------------
// Kernel 2: wprep — split weights (Wq/Wk/Wv per tap, Wo) into plain hi/lo.
// ---------------------------------------------------------------------------
__global__ void wprep_kernel(const float* __restrict__ Wq,
                             const float* __restrict__ Wk,
                             const float* __restrict__ Wv,
                             const float* __restrict__ Wo) {
    const int tn = blockIdx.y;
    const float* W = (tn == 0) ? Wq : (tn == 1) ? Wk : (tn == 2) ? Wv : Wo;
    const int KER = (tn == 0 || tn == 1) ? 3 : 1;
    const int Kdim = DD * KER;
    const int co0 = blockIdx.x * 64;
    const int kp = threadIdx.x;              // 0..255 (ci pair)
    for (int tap = 0; tap < KER; tap++)
        for (int i = 0; i < 64; i++) {
            int co = co0 + i;
            float u = W[(size_t)co * Kdim + (2 * kp) * KER + tap];
            float vv = W[(size_t)co * Kdim + (2 * kp + 1) * KER + tap];
            uint32_t ph, pl;
            bsplit2(u, vv, ph, pl);
            g_wh[tn][tap][co][kp] = ph;
            g_wl[tn][tap][co][kp] = pl;
        }
}

// ---------------------------------------------------------------------------
// Kernel 3: conv1d as tap-decomposed bf16 MMA GEMM (split, 3 terms), LDSM
// fragment loads. Q/K epilogue -> g_qkv (fp32); V epilogue -> packed g_vh/g_vl.
// ---------------------------------------------------------------------------
#define CV_ST 20
#define CV_AH 0
#define CV_AL 2560
#define CV_BH 5120
#define CV_BL 7680
#define CV_BUF_U32 10240
#define CV_SMEM (2 * CV_BUF_U32 * (int)sizeof(uint32_t))

__global__ __launch_bounds__(256, 2)
void conv_mma(const float* __restrict__ bq, const float* __restrict__ bk,
              const float* __restrict__ bv) {
    extern __shared__ uint32_t smu[];
    __shared__ float s_bias[128];

    const int zz = blockIdx.z, tn = zz / BB, b = zz % BB;
    const float* bias = (tn == 0) ? bq : (tn == 1) ? bk : bv;
    const int KER = (tn == 2) ? 1 : 3;
    const int pad = KER >> 1;
    const int NIT = KER * 16;
    const int m0 = blockIdx.x * 128, n0 = blockIdx.y * 128;
    const int tid = threadIdx.x, wid = tid >> 5, lane = tid & 31;
    const int g = lane >> 2, tg = lane & 3;
    const int wm = (wid >> 2) * 64, wn = (wid & 3) * 32;
    const int lt = lane >> 3, ro = lane & 7;   // ldsm tile index, row offset

    if (tid < 128) s_bias[tid] = bias[m0 + tid];

    const uint32_t sbase = (uint32_t)__cvta_generic_to_shared(smu);

    float4 dacc[4][4];
    #pragma unroll
    for (int mi = 0; mi < 4; mi++)
        #pragma unroll
        for (int ni = 0; ni < 4; ni++) dacc[mi][ni] = make_float4(0.f, 0.f, 0.f, 0.f);

    const int a_row = tid >> 1, a_half = (tid & 1) * 8;
    const int b_s = tid & 127, b_half = (tid >> 7) * 8;

    uint4 rah0, rah1, ral0, ral1, rbh0, rbh1, rbl0, rbl1;

    auto ldg_slab = [&](int it) {
        int tap = it >> 4, c = it & 15;
        const uint32_t* wh = &g_wh[tn][tap][m0 + a_row][c * 16 + a_half];
        const uint32_t* wl = &g_wl[tn][tap][m0 + a_row][c * 16 + a_half];
        rah0 = *(const uint4*)&wh[0]; rah1 = *(const uint4*)&wh[4];
        ral0 = *(const uint4*)&wl[0]; ral1 = *(const uint4*)&wl[4];
        int s_glob = n0 + b_s + tap - pad;
        if ((unsigned)s_glob < (unsigned)SS) {
            const uint32_t* xh = &g_xh[tn][b][s_glob][c * 16 + b_half];
            const uint32_t* xl = &g_xl[tn][b][s_glob][c * 16 + b_half];
            rbh0 = *(const uint4*)&xh[0]; rbh1 = *(const uint4*)&xh[4];
            rbl0 = *(const uint4*)&xl[0]; rbl1 = *(const uint4*)&xl[4];
        } else {
            rbh0 = make_uint4(0, 0, 0, 0); rbh1 = rbh0;
            rbl0 = rbh0; rbl1 = rbh0;
        }
    };
    auto sts_slab = [&](int bf) {
        uint32_t* Ah = smu + bf * CV_BUF_U32 + CV_AH + a_row * CV_ST + a_half;
        uint32_t* Al = smu + bf * CV_BUF_U32 + CV_AL + a_row * CV_ST + a_half;
        uint32_t* Bh = smu + bf * CV_BUF_U32 + CV_BH + b_s * CV_ST + b_half;
        uint32_t* Bl = smu + bf * CV_BUF_U32 + CV_BL + b_s * CV_ST + b_half;
        *(uint4*)&Ah[0] = rah0; *(uint4*)&Ah[4] = rah1;
        *(uint4*)&Al[0] = ral0; *(uint4*)&Al[4] = ral1;
        *(uint4*)&Bh[0] = rbh0; *(uint4*)&Bh[4] = rbh1;
        *(uint4*)&Bl[0] = rbl0; *(uint4*)&Bl[4] = rbl1;
    };

    ldg_slab(0);
    sts_slab(0);
    __syncthreads();

    for (int it = 0; it < NIT; it++) {
        const int bf = it & 1;
        const bool have = (it + 1) < NIT;
        if (have) ldg_slab(it + 1);

        const uint32_t bufB = sbase + 4 * (bf * CV_BUF_U32);
        #pragma unroll
        for (int s = 0; s < 2; s++) {
            uint32_t bh[4][2], bl[4][2];
            #pragma unroll
            for (int p = 0; p < 2; p++) {
                uint32_t off = (wn + (2 * p + (lt >> 1)) * 8 + ro) * CV_ST
                             + s * 8 + (lt & 1) * 4;
                uint32_t r0, r1, r2, r3;
                ldsm4(r0, r1, r2, r3, bufB + 4 * (CV_BH + off));
                bh[2 * p][0] = r0; bh[2 * p][1] = r1;
                bh[2 * p + 1][0] = r2; bh[2 * p + 1][1] = r3;
                ldsm4(r0, r1, r2, r3, bufB + 4 * (CV_BL + off));
                bl[2 * p][0] = r0; bl[2 * p][1] = r1;
                bl[2 * p + 1][0] = r2; bl[2 * p + 1][1] = r3;
            }
            #pragma unroll
            for (int mi = 0; mi < 4; mi++) {
                uint32_t aoff = (wm + mi * 16 + (lt & 1) * 8 + ro) * CV_ST
                              + s * 8 + (lt >> 1) * 4;
                uint32_t a0, a1, a2, a3, l0, l1, l2, l3;
                ldsm4(a0, a1, a2, a3, bufB + 4 * (CV_AH + aoff));
                ldsm4(l0, l1, l2, l3, bufB + 4 * (CV_AL + aoff));
                #pragma unroll
                for (int ni = 0; ni < 4; ni++) {
                    mma_bf16s(dacc[mi][ni], a0, a1, a2, a3, bh[ni][0], bh[ni][1]);
                    mma_bf16s(dacc[mi][ni], a0, a1, a2, a3, bl[ni][0], bl[ni][1]);
                    mma_bf16s(dacc[mi][ni], l0, l1, l2, l3, bh[ni][0], bh[ni][1]);
                }
            }
        }

        if (have) sts_slab(bf ^ 1);
        __syncthreads();
    }

    if (tn != 2) {
        float* out = &g_qkv[tn][b][0][0];
        #pragma unroll
        for (int mi = 0; mi < 4; mi++) {
            int lr0 = wm + mi * 16 + g;
            float b0 = s_bias[lr0], b1 = s_bias[lr0 + 8];
            #pragma unroll
            for (int ni = 0; ni < 4; ni++) {
                int col = n0 + wn + ni * 8 + 2 * tg;
                float4 d = dacc[mi][ni];
                *(float2*)&out[(size_t)(m0 + lr0) * SS + col] =
                    make_float2(d.x + b0, d.y + b0);
                *(float2*)&out[(size_t)(m0 + lr0 + 8) * SS + col] =
                    make_float2(d.z + b1, d.w + b1);
            }
        }
    } else {
        // V: emit packed bf16 hi/lo directly (kpair over s = adjacent cols)
        #pragma unroll
        for (int mi = 0; mi < 4; mi++) {
            int lr0 = wm + mi * 16 + g;
            float b0 = s_bias[lr0], b1 = s_bias[lr0 + 8];
            int row0 = m0 + lr0, row1 = row0 + 8;
            int bh0 = b * HH + (row0 >> 6), bh1 = b * HH + (row1 >> 6);
            int dd0 = row0 & 63, dd1 = row1 & 63;
            #pragma unroll
            for (int ni = 0; ni < 4; ni++) {
                int kp = (n0 + wn + ni * 8 + 2 * tg) >> 1;
                float4 d = dacc[mi][ni];
                uint32_t ph, pl;
                bsplit2(d.x + b0, d.y + b0, ph, pl);
                g_vh[bh0][dd0][kp] = ph; g_vl[bh0][dd0][kp] = pl;
                bsplit2(d.z + b1, d.w + b1, ph, pl);
                g_vh[bh1][dd1][kp] = ph; g_vl[bh1][dd1][kp] = pl;
            }
        }
    }
}

// ---------------------------------------------------------------------------
// Kernel 4: qkprep — split Q (x 1/64) and K into plain kpair-packed hi/lo.
// ---------------------------------------------------------------------------
__global__ void qkprep_kernel() {
    __shared__ float tile[32][33];
    int zz = blockIdx.z;
    int tn = zz / BB, b = zz % BB;     // tn: 0=Q, 1=K
    const float* src = &g_qkv[tn][b][0][0];
    int s0 = blockIdx.x * 32, d0 = blockIdx.y * 32;
    int tx = threadIdx.x, ty = threadIdx.y;
    #pragma unroll
    for (int i = ty; i < 32; i += 8)
        tile[i][tx] = src[(size_t)(d0 + i) * SS + s0 + tx];
    __syncthreads();

    const float scale = (tn == 0) ? 0.015625f : 1.0f;
    const int h = d0 >> 6;
    const int kp_base = (d0 & 63) >> 1;
    const int bh = b * HH + h;
    uint32_t* dh = (tn == 0) ? &g_sqh[bh][0][0] : &g_skh[bh][0][0];
    uint32_t* dl = (tn == 0) ? &g_sql[bh][0][0] : &g_skl[bh][0][0];

    const int kpl = tx & 15;
    const int half = tx >> 4;
    const int pos = kp_base + kpl;
    #pragma unroll
    for (int i = ty; i < 32; i += 8) {
        float u = tile[2 * kpl][i] * scale;
        float v = tile[2 * kpl + 1][i] * scale;
        uint32_t ph, pl;
        bsplit2(u, v, ph, pl);
        if (half == 0) dh[(size_t)(s0 + i) * 32 + pos] = ph;
        else           dl[(size_t)(s0 + i) * 32 + pos] = pl;
    }
}

// ---------------------------------------------------------------------------
// Kernel 5: scores GEMM via bf16 mma (3 terms), LDSM fragment loads.
// smem stride 36 u32. Raw scores -> g_p.
// ---------------------------------------------------------------------------
#define SG_ST 36
#define SG_A_H 0
#define SG_A_L 4608
#define SG_B_H 9216
#define SG_B_L 13824
#define SG_SMEM (18432 * (int)sizeof(uint32_t))

__global__ __launch_bounds__(256, 2) void scores_gemm() {
    extern __shared__ uint32_t smu[];
    const int b = blockIdx.z, h = blockIdx.y;
    const int s0 = (blockIdx.x >> 3) * 128, t0 = (blockIdx.x & 7) * 128;
    const int bh = b * HH + h;
    const int tid = threadIdx.x, wid = tid >> 5, lane = tid & 31;
    const int g = lane >> 2, tg = lane & 3;
    const int wm = (wid >> 2) * 64, wn = (wid & 3) * 32;
    const int lt = lane >> 3, ro = lane & 7;

    const uint32_t sbase = (uint32_t)__cvta_generic_to_shared(smu);

    {
        const int row = tid >> 1, c0 = (tid & 1) * 16;
        const uint32_t* sa_h = &g_sqh[bh][s0 + row][c0];
        const uint32_t* sa_l = &g_sql[bh][s0 + row][c0];
        const uint32_t* sb_h = &g_skh[bh][t0 + row][c0];
        const uint32_t* sb_l = &g_skl[bh][t0 + row][c0];
        uint32_t* Ah = smu + SG_A_H + row * SG_ST + c0;
        uint32_t* Al = smu + SG_A_L + row * SG_ST + c0;
        uint32_t* Bh = smu + SG_B_H + row * SG_ST + c0;
        uint32_t* Bl = smu + SG_B_L + row * SG_ST + c0;
        #pragma unroll
        for (int i = 0; i < 4; i++) {
            *(uint4*)&Ah[4 * i] = *(const uint4*)&sa_h[4 * i];
            *(uint4*)&Al[4 * i] = *(const uint4*)&sa_l[4 * i];
            *(uint4*)&Bh[4 * i] = *(const uint4*)&sb_h[4 * i];
            *(uint4*)&Bl[4 * i] = *(const uint4*)&sb_l[4 * i];
        }
    }
    __syncthreads();

    float4 dacc[4][4];
    #pragma unroll
    for (int mi = 0; mi < 4; mi++)
        #pragma unroll
        for (int ni = 0; ni < 4; ni++) dacc[mi][ni] = make_float4(0.f, 0.f, 0.f, 0.f);

    #pragma unroll
    for (int s = 0; s < 4; s++) {
        uint32_t bh2[4][2], bl2[4][2];
        #pragma unroll
        for (int p = 0; p < 2; p++) {
            uint32_t off = (wn + (2 * p + (lt >> 1)) * 8 + ro) * SG_ST
                         + s * 8 + (lt & 1) * 4;
            uint32_t r0, r1, r2, r3;
            ldsm4(r0, r1, r2, r3, sbase + 4 * (SG_B_H + off));
            bh2[2 * p][0] = r0; bh2[2 * p][1] = r1;
            bh2[2 * p + 1][0] = r2; bh2[2 * p + 1][1] = r3;
            ldsm4(r0, r1, r2, r3, sbase + 4 * (SG_B_L + off));
            bl2[2 * p][0] = r0; bl2[2 * p][1] = r1;
            bl2[2 * p + 1][0] = r2; bl2[2 * p + 1][1] = r3;
        }
        #pragma unroll
        for (int mi = 0; mi < 4; mi++) {
            uint32_t aoff = (wm + mi * 16 + (lt & 1) * 8 + ro) * SG_ST
                          + s * 8 + (lt >> 1) * 4;
            uint32_t a0, a1, a2, a3, l0, l1, l2, l3;
            ldsm4(a0, a1, a2, a3, sbase + 4 * (SG_A_H + aoff));
            ldsm4(l0, l1, l2, l3, sbase + 4 * (SG_A_L + aoff));
            #pragma unroll
            for (int ni = 0; ni < 4; ni++) {
                mma_bf16s(dacc[mi][ni], a0, a1, a2, a3, bh2[ni][0], bh2[ni][1]);
                mma_bf16s(dacc[mi][ni], a0, a1, a2, a3, bl2[ni][0], bl2[ni][1]);
                mma_bf16s(dacc[mi][ni], l0, l1, l2, l3, bh2[ni][0], bh2[ni][1]);
            }
        }
    }

    float* Pg = &g_p[((size_t)bh << 20)];
    #pragma unroll
    for (int mi = 0; mi < 4; mi++) {
        int lr0 = s0 + wm + mi * 16 + g;
        #pragma unroll
        for (int ni = 0; ni < 4; ni++) {
            int col = t0 + wn + ni * 8 + 2 * tg;
            float4 d = dacc[mi][ni];
            *(float2*)&Pg[(size_t)lr0 * SS + col]       = make_float2(d.x, d.y);
            *(float2*)&Pg[(size_t)(lr0 + 8) * SS + col] = make_float2(d.z, d.w);
        }
    }
}

// ---------------------------------------------------------------------------
// Kernel 6: softmax + fused ave + plain packed bf16 split P emission.
// 64KB smem, min 3 CTAs/SM.
// ---------------------------------------------------------------------------
#define SMA_SMEM (16384 * (int)sizeof(float))

__global__ __launch_bounds__(256, 3) void softmax_ave(float* __restrict__ ave) {
    extern __shared__ float smf[];
    float* buf = smf;            // 8*1024
    float* av  = smf + 8192;     // 8*1024

    const int b = blockIdx.y, s0 = blockIdx.x * 8;
    const int tid = threadIdx.x, w = tid >> 5, lane = tid & 31;

    #pragma unroll
    for (int i = 0; i < 8; i++)
        *(float4*)&av[(i * 256 + tid) * 4] = make_float4(0.f, 0.f, 0.f, 0.f);

    for (int h = 0; h < HH; h++) {
        const int bh = b * HH + h;
        const float* Pg = &g_p[(((size_t)bh) << 20) + (size_t)s0 * SS];
        __syncthreads();
        #pragma unroll
        for (int i = 0; i < 8; i++) {
            int off = (i * 256 + tid) * 4;
            *(float4*)&buf[off] = *(const float4*)&Pg[off];
        }
        __syncthreads();

        {
            float* row = &buf[w * 1024];
            float* arow = &av[w * 1024];
            float m = -1e30f;
            for (int j = lane; j < 1024; j += 32) m = fmaxf(m, row[j]);
            #pragma unroll
            for (int o = 16; o > 0; o >>= 1)
                m = fmaxf(m, __shfl_xor_sync(0xffffffffu, m, o));
            float s = 0.0f;
            for (int j = lane; j < 1024; j += 32) {
                float e = __expf(row[j] - m);
                row[j] = e;
                s += e;
            }
            #pragma unroll
            for (int o = 16; o > 0; o >>= 1) s += __shfl_xor_sync(0xffffffffu, s, o);
            float inv = 1.0f / s;
            for (int j = lane; j < 1024; j += 32) {
                float p = row[j] * inv;
                row[j] = p;
                arow[j] += 0.125f * p;
            }
        }
        __syncthreads();

        #pragma unroll
        for (int i = 0; i < 16; i++) {
            int tt = i * 256 + tid;          // 0..4095
            int r = tt >> 9, kk = tt & 511;
            float2 uv = *(float2*)&buf[r * 1024 + 2 * kk];
            uint32_t ph, pl;
            bsplit2(uv.x, uv.y, ph, pl);
            g_ph[bh][s0 + r][kk] = ph;
            g_pl[bh][s0 + r][kk] = pl;
        }
    }

    __syncthreads();
    #pragma unroll
    for (int i = 0; i < 8; i++) {
        int off = (i * 256 + tid) * 4;
        int r = off >> 10, c = off & 1023;
        *(float4*)&ave[((size_t)b * SS + s0 + r) * SS + c] = *(float4*)&av[off];
    }
}

// ---------------------------------------------------------------------------
// Kernel 7: PV GEMM via bf16 mma (3 terms), LDSM fragment loads.
// smem stride 20 u32. Epilogue emits plain packed o1.
// ---------------------------------------------------------------------------
#define PV_ST 20
#define PV_A_H 0
#define PV_A_L 2560
#define PV_B_H 5120
#define PV_B_L 6400
#define PV_BUF_U32 7680
#define PV_SMEM (2 * PV_BUF_U32 * (int)sizeof(uint32_t))

__global__ __launch_bounds__(256, 2) void pv_mma() {
    extern __shared__ uint32_t smu[];
    const int b = blockIdx.z, h = blockIdx.y, s0 = blockIdx.x * 128;
    const int bh = b * HH + h;
    const int tid = threadIdx.x, wid = tid >> 5, lane = tid & 31;
    const int g = lane >> 2, tg = lane & 3;
    const int wm = (wid >> 2) * 64, wn = (wid & 3) * 16;
    const int lt = lane >> 3, ro = lane & 7;

    const uint32_t sbase = (uint32_t)__cvta_generic_to_shared(smu);

    float4 dacc[4][2];
    #pragma unroll
    for (int mi = 0; mi < 4; mi++)
        #pragma unroll
        for (int ni = 0; ni < 2; ni++) dacc[mi][ni] = make_float4(0.f, 0.f, 0.f, 0.f);

    const int a_row = tid >> 1, a_c0 = (tid & 1) * 8;
    const int b_d = tid >> 2, b_c0 = (tid & 3) * 4;

    uint4 rah0, rah1, ral0, ral1, rbh, rbl;

    auto ldg_slab = [&](int c) {
        const uint32_t* ph = &g_ph[bh][s0 + a_row][c * 16 + a_c0];
        const uint32_t* pl = &g_pl[bh][s0 + a_row][c * 16 + a_c0];
        rah0 = *(const uint4*)&ph[0]; rah1 = *(const uint4*)&ph[4];
        ral0 = *(const uint4*)&pl[0]; ral1 = *(const uint4*)&pl[4];
        rbh = *(const uint4*)&g_vh[bh][b_d][c * 16 + b_c0];
        rbl = *(const uint4*)&g_vl[bh][b_d][c * 16 + b_c0];
    };
    auto sts_slab = [&](int bf) {
        uint32_t* Ah = smu + bf * PV_BUF_U32 + PV_A_H + a_row * PV_ST + a_c0;
        uint32_t* Al = smu + bf * PV_BUF_U32 + PV_A_L + a_row * PV_ST + a_c0;
        uint32_t* Bh = smu + bf * PV_BUF_U32 + PV_B_H + b_d * PV_ST + b_c0;
        uint32_t* Bl = smu + bf * PV_BUF_U32 + PV_B_L + b_d * PV_ST + b_c0;
        *(uint4*)&Ah[0] = rah0; *(uint4*)&Ah[4] = rah1;
        *(uint4*)&Al[0] = ral0; *(uint4*)&Al[4] = ral1;
        *(uint4*)&Bh[0] = rbh;
        *(uint4*)&Bl[0] = rbl;
    };

    ldg_slab(0);
    sts_slab(0);
    __syncthreads();

    for (int c = 0; c < 32; c++) {
        const int bf = c & 1;
        const bool have = (c + 1) < 32;
        if (have) ldg_slab(c + 1);

        const uint32_t bufB = sbase + 4 * (bf * PV_BUF_U32);
        #pragma unroll
        for (int s = 0; s < 2; s++) {
            uint32_t bh2[2][2], bl2[2][2];
            {
                uint32_t off = (wn + (lt >> 1) * 8 + ro) * PV_ST
                             + s * 8 + (lt & 1) * 4;
                uint32_t r0, r1, r2, r3;
                ldsm4(r0, r1, r2, r3, bufB + 4 * (PV_B_H + off));
                bh2[0][0] = r0; bh2[0][1] = r1; bh2[1][0] = r2; bh2[1][1] = r3;
                ldsm4(r0, r1, r2, r3, bufB + 4 * (PV_B_L + off));
                bl2[0][0] = r0; bl2[0][1] = r1; bl2[1][0] = r2; bl2[1][1] = r3;
            }
            #pragma unroll
            for (int mi = 0; mi < 4; mi++) {
                uint32_t aoff = (wm + mi * 16 + (lt & 1) * 8 + ro) * PV_ST
                              + s * 8 + (lt >> 1) * 4;
                uint32_t a0, a1, a2, a3, l0, l1, l2, l3;
                ldsm4(a0, a1, a2, a3, bufB + 4 * (PV_A_H + aoff));
                ldsm4(l0, l1, l2, l3, bufB + 4 * (PV_A_L + aoff));
                #pragma unroll
                for (int ni = 0; ni < 2; ni++) {
                    mma_bf16s(dacc[mi][ni], a0, a1, a2, a3, bh2[ni][0], bh2[ni][1]);
                    mma_bf16s(dacc[mi][ni], a0, a1, a2, a3, bl2[ni][0], bl2[ni][1]);
                    mma_bf16s(dacc[mi][ni], l0, l1, l2, l3, bh2[ni][0], bh2[ni][1]);
                }
            }
        }

        if (have) sts_slab(bf ^ 1);
        __syncthreads();
    }

    // epilogue: pack (col, col+1) pairs = one kpair over d (plain order)
    #pragma unroll
    for (int mi = 0; mi < 4; mi++) {
        int lr0 = s0 + wm + mi * 16 + g;
        int row0 = b * SS + lr0, row1 = row0 + 8;
        #pragma unroll
        for (int ni = 0; ni < 2; ni++) {
            int kp = (h * HD + wn + ni * 8 + 2 * tg) >> 1;
            float4 d = dacc[mi][ni];
            uint32_t ph, pl;
            bsplit2(d.x, d.y, ph, pl);
            g_oh[row0][kp] = ph; g_ol[row0][kp] = pl;
            bsplit2(d.z, d.w, ph, pl);
            g_oh[row1][kp] = ph; g_ol[row1][kp] = pl;
        }
    }
}

// ---------------------------------------------------------------------------
// Kernel 8: output projection via bf16 mma (3 terms), LDSM fragment loads.
// ---------------------------------------------------------------------------
__global__ __launch_bounds__(256, 2) void proj_mma(const float* __restrict__ bo,
                                                   float* __restrict__ out) {
    extern __shared__ uint32_t smu[];
    const int m0 = blockIdx.x * 128, n0 = blockIdx.y * 128;
    const int tid = threadIdx.x, wid = tid >> 5, lane = tid & 31;
    const int g = lane >> 2, tg = lane & 3;
    const int wm = (wid >> 2) * 64, wn = (wid & 3) * 32;
    const int lt = lane >> 3, ro = lane & 7;

    const uint32_t sbase = (uint32_t)__cvta_generic_to_shared(smu);

    float4 dacc[4][4];
    #pragma unroll
    for (int mi = 0; mi < 4; mi++)
        #pragma unroll
        for (int ni = 0; ni < 4; ni++) dacc[mi][ni] = make_float4(0.f, 0.f, 0.f, 0.f);

    const int a_row = tid >> 1, a_half = (tid & 1) * 8;

    uint4 rah0, rah1, ral0, ral1, rbh0, rbh1, rbl0, rbl1;

    auto ldg_slab = [&](int c) {
        const uint32_t* oh = &g_oh[m0 + a_row][c * 16 + a_half];
        const uint32_t* ol = &g_ol[m0 + a_row][c * 16 + a_half];
        rah0 = *(const uint4*)&oh[0]; rah1 = *(const uint4*)&oh[4];
        ral0 = *(const uint4*)&ol[0]; ral1 = *(const uint4*)&ol[4];
        const uint32_t* wh = &g_wh[3][0][n0 + a_row][c * 16 + a_half];
        const uint32_t* wl = &g_wl[3][0][n0 + a_row][c * 16 + a_half];
        rbh0 = *(const uint4*)&wh[0]; rbh1 = *(const uint4*)&wh[4];
        rbl0 = *(const uint4*)&wl[0]; rbl1 = *(const uint4*)&wl[4];
    };
    auto sts_slab = [&](int bf) {
        uint32_t* Ah = smu + bf * CV_BUF_U32 + CV_AH + a_row * CV_ST + a_half;
        uint32_t* Al = smu + bf * CV_BUF_U32 + CV_AL + a_row * CV_ST + a_half;
        uint32_t* Bh = smu + bf * CV_BUF_U32 + CV_BH + a_row * CV_ST + a_half;
        uint32_t* Bl = smu + bf * CV_BUF_U32 + CV_BL + a_row * CV_ST + a_half;
        *(uint4*)&Ah[0] = rah0; *(uint4*)&Ah[4] = rah1;
        *(uint4*)&Al[0] = ral0; *(uint4*)&Al[4] = ral1;
        *(uint4*)&Bh[0] = rbh0; *(uint4*)&Bh[4] = rbh1;
        *(uint4*)&Bl[0] = rbl0; *(uint4*)&Bl[4] = rbl1;
    };

    ldg_slab(0);
    sts_slab(0);
    __syncthreads();

    for (int c = 0; c < 16; c++) {
        const int bf = c & 1;
        const bool have = (c + 1) < 16;
        if (have) ldg_slab(c + 1);

        const uint32_t bufB = sbase + 4 * (bf * CV_BUF_U32);
        #pragma unroll
        for (int s = 0; s < 2; s++) {
            uint32_t bh[4][2], bl[4][2];
            #pragma unroll
            for (int p = 0; p < 2; p++) {
                uint32_t off = (wn + (2 * p + (lt >> 1)) * 8 + ro) * CV_ST
                             + s * 8 + (lt & 1) * 4;
                uint32_t r0, r1, r2, r3;
                ldsm4(r0, r1, r2, r3, bufB + 4 * (CV_BH + off));
                bh[2 * p][0] = r0; bh[2 * p][1] = r1;
                bh[2 * p + 1][0] = r2; bh[2 * p + 1][1] = r3;
                ldsm4(r0, r1, r2, r3, bufB + 4 * (CV_BL + off));
                bl[2 * p][0] = r0; bl[2 * p][1] = r1;
                bl[2 * p + 1][0] = r2; bl[2 * p + 1][1] = r3;
            }
            #pragma unroll
            for (int mi = 0; mi < 4; mi++) {
                uint32_t aoff = (wm + mi * 16 + (lt & 1) * 8 + ro) * CV_ST
                              + s * 8 + (lt >> 1) * 4;
                uint32_t a0, a1, a2, a3, l0, l1, l2, l3;
                ldsm4(a0, a1, a2, a3, bufB + 4 * (CV_AH + aoff));
                ldsm4(l0, l1, l2, l3, bufB + 4 * (CV_AL + aoff));
                #pragma unroll
                for (int ni = 0; ni < 4; ni++) {
                    mma_bf16s(dacc[mi][ni], a0, a1, a2, a3, bh[ni][0], bh[ni][1]);
                    mma_bf16s(dacc[mi][ni], a0, a1, a2, a3, bl[ni][0], bl[ni][1]);
                    mma_bf16s(dacc[mi][ni], l0, l1, l2, l3, bh[ni][0], bh[ni][1]);
                }
            }
        }

        if (have) sts_slab(bf ^ 1);
        __syncthreads();
    }

    #pragma unroll
    for (int mi = 0; mi < 4; mi++) {
        int lr0 = m0 + wm + mi * 16 + g;
        #pragma unroll
        for (int ni = 0; ni < 4; ni++) {
            int col = n0 + wn + ni * 8 + 2 * tg;
            float2 bb = *(const float2*)&bo[col];
            float4 d = dacc[mi][ni];
            *(float2*)&out[(size_t)lr0 * DD + col]       = make_float2(d.x + bb.x, d.y + bb.y);
            *(float2*)&out[(size_t)(lr0 + 8) * DD + col] = make_float2(d.z + bb.x, d.w + bb.y);
        }
    }
}

// ---------------------------------------------------------------------------
extern "C" void kernel_launch(void* const* d_in, const int* in_sizes, int n_in,
                              void* d_out, int out_size) {
    const float* query = (const float*)d_in[0];
    const float* key_t = (const float*)d_in[1];
    const float* value = (const float*)d_in[2];
    const float* Wq    = (const float*)d_in[3];
    const float* bq    = (const float*)d_in[4];
    const float* Wk    = (const float*)d_in[5];
    const float* bk    = (const float*)d_in[6];
    const float* Wv    = (const float*)d_in[7];
    const float* bv    = (const float*)d_in[8];
    const float* Wo    = (const float*)d_in[9];
    const float* bo    = (const float*)d_in[10];

    float* out = (float*)d_out;
    float* ave = out + (size_t)BB * SS * DD;

    cudaFuncSetAttribute(conv_mma, cudaFuncAttributeMaxDynamicSharedMemorySize, CV_SMEM);
    cudaFuncSetAttribute(scores_gemm, cudaFuncAttributeMaxDynamicSharedMemorySize, SG_SMEM);
    cudaFuncSetAttribute(softmax_ave, cudaFuncAttributeMaxDynamicSharedMemorySize, SMA_SMEM);
    cudaFuncSetAttribute(pv_mma, cudaFuncAttributeMaxDynamicSharedMemorySize, PV_SMEM);
    cudaFuncSetAttribute(proj_mma, cudaFuncAttributeMaxDynamicSharedMemorySize, CV_SMEM);

    xprep_kernel<<<dim3(SS / 128, BB, 3), 256>>>(query, key_t, value);
    wprep_kernel<<<dim3(DD / 64, 4), 256>>>(Wq, Wk, Wv, Wo);
    conv_mma<<<dim3(DD / 128, SS / 128, 3 * BB), 256, CV_SMEM>>>(bq, bk, bv);
    qkprep_kernel<<<dim3(SS / 32, DD / 32, 2 * BB), dim3(32, 8)>>>();
    scores_gemm<<<dim3(64, HH, BB), 256, SG_SMEM>>>();
    softmax_ave<<<dim3(SS / 8, BB), 256, SMA_SMEM>>>(ave);
    pv_mma<<<dim3(SS / 128, HH, BB), 256, PV_SMEM>>>();
    proj_mma<<<dim3((BB * SS) / 128, DD / 128), 256, CV_SMEM>>>(bo, out);
}